// round 14
// baseline (speedup 1.0000x reference)
#include <cuda_runtime.h>
#include <cuda_bf16.h>
#include <cstdint>

// Problem constants
#define BB 256   // batch
#define MM 96    // memory slots
#define WW 128   // write tokens
#define DD 512   // embed dim

// ---------------- scratch (static device globals: allocation-free) ----------
__device__ __nv_bfloat16 g_wtok_bf[BB * WW * DD];
__device__ __nv_bfloat16 g_mem_bf[BB * MM * DD];
__device__ __nv_bfloat16 g_Wq_bf[DD * DD];
__device__ __nv_bfloat16 g_Wk_bf[DD * DD];
__device__ __nv_bfloat16 g_We_bf[DD * DD];
__device__ __nv_bfloat16 g_Wa_bf[DD * DD];

__device__ __nv_bfloat16 g_qb[BB * WW * DD];   // q bf16 (scores input)
__device__ __nv_bfloat16 g_kb[BB * MM * DD];   // k bf16 (scores input)
__device__ float g_e[BB * WW * DD];
__device__ float g_a[BB * WW * DD];            // NEGATED tanh (scan convention)
__device__ float g_s[BB * WW * MM];

static __device__ __forceinline__ uint32_t smem_u32(const void* p) {
    uint32_t a;
    asm("{ .reg .u64 t; cvta.to.shared.u64 t, %1; cvt.u32.u64 %0, t; }" : "=r"(a) : "l"(p));
    return a;
}

static __device__ __forceinline__ unsigned long long pk2(float x, float y) {
    unsigned long long r;
    asm("mov.b64 %0, {%1, %2};" : "=l"(r) : "f"(x), "f"(y));
    return r;
}
static __device__ __forceinline__ void upk2(float& x, float& y, unsigned long long r) {
    asm("mov.b64 {%0, %1}, %2;" : "=f"(x), "=f"(y) : "l"(r));
}
static __device__ __forceinline__ unsigned long long fma2(
    unsigned long long a, unsigned long long b, unsigned long long c) {
    unsigned long long d;
    asm("fma.rn.f32x2 %0, %1, %2, %3;" : "=l"(d) : "l"(a), "l"(b), "l"(c));
    return d;
}

// ---------------------------------------------------------------------------
// fp32 -> bf16: ALL conversions (wtok + memory + 4 weights) in one launch
// ---------------------------------------------------------------------------
#define N4_WT (BB * WW * DD / 4)   // 4194304
#define N4_MEM (BB * MM * DD / 4)  // 3145728
#define N4_W (DD * DD / 4)         // 65536

__global__ __launch_bounds__(256) void f2bf_all_kernel(
    const float4* __restrict__ wt, uint2* __restrict__ wtd,
    const float4* __restrict__ mem, uint2* __restrict__ memd,
    const float4* __restrict__ w0, const float4* __restrict__ w1,
    const float4* __restrict__ w2, const float4* __restrict__ w3,
    uint2* __restrict__ wd0, uint2* __restrict__ wd1,
    uint2* __restrict__ wd2, uint2* __restrict__ wd3)
{
    const int ntot = N4_WT + N4_MEM + 4 * N4_W;
    int i = blockIdx.x * 256 + threadIdx.x;
    const int stride = gridDim.x * 256;
    for (; i < ntot; i += stride) {
        const float4* src;
        uint2* dst;
        int off;
        if (i < N4_WT) { src = wt; dst = wtd; off = i; }
        else if (i < N4_WT + N4_MEM) { src = mem; dst = memd; off = i - N4_WT; }
        else {
            int j = i - N4_WT - N4_MEM;
            int mat = j >> 16;
            off = j & (N4_W - 1);
            src = (mat == 0) ? w0 : (mat == 1) ? w1 : (mat == 2) ? w2 : w3;
            dst = (mat == 0) ? wd0 : (mat == 1) ? wd1 : (mat == 2) ? wd2 : wd3;
        }
        float4 v = src[off];
        __nv_bfloat162 lo = __floats2bfloat162_rn(v.x, v.y);
        __nv_bfloat162 hi = __floats2bfloat162_rn(v.z, v.w);
        uint2 o;
        o.x = *(uint32_t*)&lo;
        o.y = *(uint32_t*)&hi;
        dst[off] = o;
    }
}

// ---------------------------------------------------------------------------
// mma.sync GEMM core: C = act(A @ Bw^T + bias)
// Tile 128x128x32, 256 threads, warp tile 64x32, m16n8k16 bf16.
// 3-stage cp.async pipeline, ONE __syncthreads per K-step.
// act: 1=sigmoid fp32, 2=NEGATED tanh fp32, 3=none bf16 out
// ---------------------------------------------------------------------------
#define GBM 128
#define GBN 128
#define GBK 32
#define LDSK 40
#define NKT (DD / GBK)            // 16
#define GEMM_ASTG (GBM * LDSK)    // bf16 elems per A stage (5120)
#define GEMM_BSTG (GBN * LDSK)
#define GEMM_SMEM ((3 * GEMM_ASTG + 3 * GEMM_BSTG) * 2)   // 61440 B

static __device__ __forceinline__ void gemm_tile(
    const __nv_bfloat16* __restrict__ A,
    const __nv_bfloat16* __restrict__ Bw,
    const float* __restrict__ bias,
    void* __restrict__ Cv,
    long rowbase, int colbase, int act)
{
    extern __shared__ __align__(128) char dsm[];
    const uint32_t sA_base = smem_u32(dsm);
    const uint32_t sB_base = sA_base + 3 * GEMM_ASTG * 2;

    const int tid = threadIdx.x;
    const int wid = tid >> 5;
    const int lane = tid & 31;
    const int wm = wid & 1;
    const int wn = wid >> 1;

    float acc[4][4][4];
#pragma unroll
    for (int mi = 0; mi < 4; mi++)
#pragma unroll
        for (int ni = 0; ni < 4; ni++)
#pragma unroll
            for (int v = 0; v < 4; v++) acc[mi][ni][v] = 0.f;

    const int ar0 = tid >> 2, ac0 = (tid & 3) * 8;
    const int c1 = tid + 256;
    const int ar1 = c1 >> 2, ac1 = (c1 & 3) * 8;

#define STAGE(buf, kt) do {                                                        \
    const int kk_ = (kt) * GBK;                                                    \
    const __nv_bfloat16* ga0 = A  + (rowbase + ar0) * DD + kk_ + ac0;              \
    const __nv_bfloat16* ga1 = A  + (rowbase + ar1) * DD + kk_ + ac1;              \
    const __nv_bfloat16* gb0 = Bw + (long)(colbase + ar0) * DD + kk_ + ac0;        \
    const __nv_bfloat16* gb1 = Bw + (long)(colbase + ar1) * DD + kk_ + ac1;        \
    uint32_t s_;                                                                   \
    s_ = sA_base + (uint32_t)((((buf) * GEMM_ASTG) + ar0 * LDSK + ac0) * 2);       \
    asm volatile("cp.async.cg.shared.global [%0], [%1], 16;\n" :: "r"(s_), "l"(ga0)); \
    s_ = sA_base + (uint32_t)((((buf) * GEMM_ASTG) + ar1 * LDSK + ac1) * 2);       \
    asm volatile("cp.async.cg.shared.global [%0], [%1], 16;\n" :: "r"(s_), "l"(ga1)); \
    s_ = sB_base + (uint32_t)((((buf) * GEMM_BSTG) + ar0 * LDSK + ac0) * 2);       \
    asm volatile("cp.async.cg.shared.global [%0], [%1], 16;\n" :: "r"(s_), "l"(gb0)); \
    s_ = sB_base + (uint32_t)((((buf) * GEMM_BSTG) + ar1 * LDSK + ac1) * 2);       \
    asm volatile("cp.async.cg.shared.global [%0], [%1], 16;\n" :: "r"(s_), "l"(gb1)); \
    asm volatile("cp.async.commit_group;\n");                                      \
} while (0)

    STAGE(0, 0);
    STAGE(1, 1);

    for (int kt = 0; kt < NKT; kt++) {
        if (kt == NKT - 1) asm volatile("cp.async.wait_group 0;\n");
        else               asm volatile("cp.async.wait_group 1;\n");
        __syncthreads();
        if (kt + 2 < NKT) {
            const int nb = (kt + 2) % 3;
            STAGE(nb, kt + 2);
        }

        const int buf = kt % 3;

        uint32_t af[2][4][4];
        uint32_t bfr[2][4][2];
#pragma unroll
        for (int ks = 0; ks < 2; ks++) {
            const int k0 = ks * 16;
#pragma unroll
            for (int mi = 0; mi < 4; mi++) {
                const int m0 = wm * 64 + mi * 16;
                uint32_t addr = sA_base + (uint32_t)((buf * GEMM_ASTG +
                    (m0 + (lane & 15)) * LDSK + k0 + ((lane >> 4) * 8)) * 2);
                asm volatile(
                    "ldmatrix.sync.aligned.m8n8.x4.shared.b16 {%0,%1,%2,%3}, [%4];\n"
                    : "=r"(af[ks][mi][0]), "=r"(af[ks][mi][1]),
                      "=r"(af[ks][mi][2]), "=r"(af[ks][mi][3])
                    : "r"(addr));
            }
#pragma unroll
            for (int nj = 0; nj < 2; nj++) {
                const int n0 = wn * 32 + nj * 16;
                uint32_t addr = sB_base + (uint32_t)((buf * GEMM_BSTG +
                    (n0 + (lane & 7) + ((lane >> 4) << 3)) * LDSK +
                    k0 + (((lane >> 3) & 1) * 8)) * 2);
                uint32_t r0, r1, r2, r3;
                asm volatile(
                    "ldmatrix.sync.aligned.m8n8.x4.shared.b16 {%0,%1,%2,%3}, [%4];\n"
                    : "=r"(r0), "=r"(r1), "=r"(r2), "=r"(r3) : "r"(addr));
                bfr[ks][nj * 2][0] = r0;     bfr[ks][nj * 2][1] = r1;
                bfr[ks][nj * 2 + 1][0] = r2; bfr[ks][nj * 2 + 1][1] = r3;
            }
        }

#pragma unroll
        for (int ks = 0; ks < 2; ks++)
#pragma unroll
            for (int mi = 0; mi < 4; mi++)
#pragma unroll
                for (int ni = 0; ni < 4; ni++)
                    asm volatile(
                        "mma.sync.aligned.m16n8k16.row.col.f32.bf16.bf16.f32 "
                        "{%0,%1,%2,%3}, {%4,%5,%6,%7}, {%8,%9}, {%0,%1,%2,%3};\n"
                        : "+f"(acc[mi][ni][0]), "+f"(acc[mi][ni][1]),
                          "+f"(acc[mi][ni][2]), "+f"(acc[mi][ni][3])
                        : "r"(af[ks][mi][0]), "r"(af[ks][mi][1]),
                          "r"(af[ks][mi][2]), "r"(af[ks][mi][3]),
                          "r"(bfr[ks][ni][0]), "r"(bfr[ks][ni][1]));
    }
#undef STAGE

    // epilogue: bias + activation (runtime act)
#pragma unroll
    for (int mi = 0; mi < 4; mi++) {
        const long r0 = rowbase + wm * 64 + mi * 16 + (lane >> 2);
#pragma unroll
        for (int ni = 0; ni < 4; ni++) {
            const int col = colbase + wn * 32 + ni * 8 + (lane & 3) * 2;
            const float b0 = bias[col], b1 = bias[col + 1];
            float v0 = acc[mi][ni][0] + b0;
            float v1 = acc[mi][ni][1] + b1;
            float v2 = acc[mi][ni][2] + b0;
            float v3 = acc[mi][ni][3] + b1;
            if (act == 1) {
                v0 = 1.f / (1.f + __expf(-v0)); v1 = 1.f / (1.f + __expf(-v1));
                v2 = 1.f / (1.f + __expf(-v2)); v3 = 1.f / (1.f + __expf(-v3));
            } else if (act == 2) {
                v0 = -tanhf(v0); v1 = -tanhf(v1);   // negated for scan FFMA2 form
                v2 = -tanhf(v2); v3 = -tanhf(v3);
            }
            if (act == 3) {
                __nv_bfloat16* Cb = (__nv_bfloat16*)Cv;
                *(__nv_bfloat162*)&Cb[r0 * DD + col] = __floats2bfloat162_rn(v0, v1);
                *(__nv_bfloat162*)&Cb[(r0 + 8) * DD + col] = __floats2bfloat162_rn(v2, v3);
            } else {
                float* C = (float*)Cv;
                *(float2*)&C[r0 * DD + col] = make_float2(v0, v1);
                *(float2*)&C[(r0 + 8) * DD + col] = make_float2(v2, v3);
            }
        }
    }
}

// All 4 projections, ONE gemm_tile call site. Grid: x = (mat,col), y = rowtile.
__global__ __launch_bounds__(256) void all_gemm_kernel(
    const __nv_bfloat16* __restrict__ Awt, const __nv_bfloat16* __restrict__ Am,
    const __nv_bfloat16* __restrict__ Wq, const __nv_bfloat16* __restrict__ We,
    const __nv_bfloat16* __restrict__ Wa, const __nv_bfloat16* __restrict__ Wk,
    const float* __restrict__ bq, const float* __restrict__ be,
    const float* __restrict__ ba, const float* __restrict__ bk,
    __nv_bfloat16* __restrict__ q_out, float* __restrict__ e_out,
    float* __restrict__ a_out, __nv_bfloat16* __restrict__ k_out)
{
    const int bn = blockIdx.x;
    const int mat = bn >> 2;
    const int colbase = (bn & 3) * GBN;
    const long rowbase = (long)blockIdx.y * GBM;

    const __nv_bfloat16* Asrc;
    const __nv_bfloat16* W;
    const float* bias;
    void* Cv;
    int act;
    if (mat == 0)      { Asrc = Awt; W = Wq; bias = bq; Cv = (void*)q_out; act = 3; }
    else if (mat == 1) { Asrc = Awt; W = We; bias = be; Cv = (void*)e_out; act = 1; }
    else if (mat == 2) { Asrc = Awt; W = Wa; bias = ba; Cv = (void*)a_out; act = 2; }
    else {
        if (blockIdx.y >= BB * MM / GBM) return;   // k has 192 row tiles
        Asrc = Am; W = Wk; bias = bk; Cv = (void*)k_out; act = 3;
    }
    gemm_tile(Asrc, W, bias, Cv, rowbase, colbase, act);
}

// ---------------------------------------------------------------------------
// Fused scores + softmax (mma.sync), 3-stage pipeline, one barrier per K-step.
// ---------------------------------------------------------------------------
#define SC_QSTG (WW * LDSK)
#define SC_KSTG (MM * LDSK)
#define SC_SMEM ((3 * SC_QSTG + 3 * SC_KSTG) * 2 + 2048)

__global__ __launch_bounds__(256) void scores_softmax_kernel(
    const __nv_bfloat16* __restrict__ Q, const __nv_bfloat16* __restrict__ K,
    float* __restrict__ S)
{
    extern __shared__ __align__(128) char dsm[];
    const uint32_t sQ_base = smem_u32(dsm);
    const uint32_t sK_base = sQ_base + 3 * SC_QSTG * 2;
    float* pmax = (float*)(dsm + (3 * SC_QSTG + 3 * SC_KSTG) * 2);
    float* psum = pmax + 2 * WW;

    const int b = blockIdx.x;
    const int tid = threadIdx.x;
    const int wid = tid >> 5;
    const int lane = tid & 31;
    const int wm = wid & 3;
    const int wn = wid >> 2;

    const __nv_bfloat16* Qb = Q + (size_t)b * WW * DD;
    const __nv_bfloat16* Kb = K + (size_t)b * MM * DD;

    float acc[2][6][4];
#pragma unroll
    for (int mi = 0; mi < 2; mi++)
#pragma unroll
        for (int ni = 0; ni < 6; ni++)
#pragma unroll
            for (int v = 0; v < 4; v++) acc[mi][ni][v] = 0.f;

    const int qr0 = tid >> 2, qc0 = (tid & 3) * 8;
    const int qc1i = tid + 256;
    const int qr1 = qc1i >> 2, qc1 = (qc1i & 3) * 8;
    const int kr0 = tid >> 2, kc0 = (tid & 3) * 8;
    const int kr1 = 64 + (tid >> 2), kc1 = (tid & 3) * 8;

#define SSTAGE(buf, kt) do {                                                       \
    const int kk_ = (kt) * GBK;                                                    \
    uint32_t s_;                                                                   \
    s_ = sQ_base + (uint32_t)((((buf) * SC_QSTG) + qr0 * LDSK + qc0) * 2);         \
    asm volatile("cp.async.cg.shared.global [%0], [%1], 16;\n"                     \
                 :: "r"(s_), "l"(Qb + (size_t)qr0 * DD + kk_ + qc0));              \
    s_ = sQ_base + (uint32_t)((((buf) * SC_QSTG) + qr1 * LDSK + qc1) * 2);         \
    asm volatile("cp.async.cg.shared.global [%0], [%1], 16;\n"                     \
                 :: "r"(s_), "l"(Qb + (size_t)qr1 * DD + kk_ + qc1));              \
    s_ = sK_base + (uint32_t)((((buf) * SC_KSTG) + kr0 * LDSK + kc0) * 2);         \
    asm volatile("cp.async.cg.shared.global [%0], [%1], 16;\n"                     \
                 :: "r"(s_), "l"(Kb + (size_t)kr0 * DD + kk_ + kc0));              \
    if (tid < 128) {                                                               \
        s_ = sK_base + (uint32_t)((((buf) * SC_KSTG) + kr1 * LDSK + kc1) * 2);     \
        asm volatile("cp.async.cg.shared.global [%0], [%1], 16;\n"                 \
                     :: "r"(s_), "l"(Kb + (size_t)kr1 * DD + kk_ + kc1));          \
    }                                                                              \
    asm volatile("cp.async.commit_group;\n");                                     \
} while (0)

    SSTAGE(0, 0);
    SSTAGE(1, 1);

    for (int kt = 0; kt < NKT; kt++) {
        if (kt == NKT - 1) asm volatile("cp.async.wait_group 0;\n");
        else               asm volatile("cp.async.wait_group 1;\n");
        __syncthreads();
        if (kt + 2 < NKT) {
            const int nb = (kt + 2) % 3;
            SSTAGE(nb, kt + 2);
        }

        const int buf = kt % 3;
#pragma unroll
        for (int ks = 0; ks < 2; ks++) {
            const int k0 = ks * 16;

            uint32_t af[2][4];
#pragma unroll
            for (int mi = 0; mi < 2; mi++) {
                const int m0 = wm * 32 + mi * 16;
                uint32_t addr = sQ_base + (uint32_t)((buf * SC_QSTG +
                    (m0 + (lane & 15)) * LDSK + k0 + ((lane >> 4) * 8)) * 2);
                asm volatile(
                    "ldmatrix.sync.aligned.m8n8.x4.shared.b16 {%0,%1,%2,%3}, [%4];\n"
                    : "=r"(af[mi][0]), "=r"(af[mi][1]), "=r"(af[mi][2]), "=r"(af[mi][3])
                    : "r"(addr));
            }

            uint32_t bfr[6][2];
#pragma unroll
            for (int nj = 0; nj < 3; nj++) {
                const int n0 = wn * 48 + nj * 16;
                uint32_t addr = sK_base + (uint32_t)((buf * SC_KSTG +
                    (n0 + (lane & 7) + ((lane >> 4) << 3)) * LDSK +
                    k0 + (((lane >> 3) & 1) * 8)) * 2);
                uint32_t r0, r1, r2, r3;
                asm volatile(
                    "ldmatrix.sync.aligned.m8n8.x4.shared.b16 {%0,%1,%2,%3}, [%4];\n"
                    : "=r"(r0), "=r"(r1), "=r"(r2), "=r"(r3) : "r"(addr));
                bfr[nj * 2][0] = r0;     bfr[nj * 2][1] = r1;
                bfr[nj * 2 + 1][0] = r2; bfr[nj * 2 + 1][1] = r3;
            }

#pragma unroll
            for (int mi = 0; mi < 2; mi++)
#pragma unroll
                for (int ni = 0; ni < 6; ni++)
                    asm volatile(
                        "mma.sync.aligned.m16n8k16.row.col.f32.bf16.bf16.f32 "
                        "{%0,%1,%2,%3}, {%4,%5,%6,%7}, {%8,%9}, {%0,%1,%2,%3};\n"
                        : "+f"(acc[mi][ni][0]), "+f"(acc[mi][ni][1]),
                          "+f"(acc[mi][ni][2]), "+f"(acc[mi][ni][3])
                        : "r"(af[mi][0]), "r"(af[mi][1]), "r"(af[mi][2]), "r"(af[mi][3]),
                          "r"(bfr[ni][0]), "r"(bfr[ni][1]));
        }
    }
#undef SSTAGE

    const float scale = 0.04419417382415922f;  // 1/sqrt(512)
#pragma unroll
    for (int mi = 0; mi < 2; mi++)
#pragma unroll
        for (int ni = 0; ni < 6; ni++)
#pragma unroll
            for (int v = 0; v < 4; v++) acc[mi][ni][v] *= scale;

    int rows[2][2];
#pragma unroll
    for (int mi = 0; mi < 2; mi++) {
        rows[mi][0] = wm * 32 + mi * 16 + (lane >> 2);
        rows[mi][1] = rows[mi][0] + 8;
    }

    __syncthreads();   // smem reuse: stages dead, pmax/psum region live

#pragma unroll
    for (int mi = 0; mi < 2; mi++) {
#pragma unroll
        for (int h = 0; h < 2; h++) {
            float mx = -1e30f;
#pragma unroll
            for (int ni = 0; ni < 6; ni++) {
                mx = fmaxf(mx, acc[mi][ni][h * 2 + 0]);
                mx = fmaxf(mx, acc[mi][ni][h * 2 + 1]);
            }
            mx = fmaxf(mx, __shfl_xor_sync(0xffffffffu, mx, 1));
            mx = fmaxf(mx, __shfl_xor_sync(0xffffffffu, mx, 2));
            pmax[wn * WW + rows[mi][h]] = mx;
        }
    }
    __syncthreads();

    float inv[2][2];
#pragma unroll
    for (int mi = 0; mi < 2; mi++) {
#pragma unroll
        for (int h = 0; h < 2; h++) {
            const float gmax = fmaxf(pmax[rows[mi][h]], pmax[WW + rows[mi][h]]);
            float sm = 0.f;
#pragma unroll
            for (int ni = 0; ni < 6; ni++) {
                float e0 = __expf(acc[mi][ni][h * 2 + 0] - gmax);
                float e1 = __expf(acc[mi][ni][h * 2 + 1] - gmax);
                acc[mi][ni][h * 2 + 0] = e0;
                acc[mi][ni][h * 2 + 1] = e1;
                sm += e0 + e1;
            }
            sm += __shfl_xor_sync(0xffffffffu, sm, 1);
            sm += __shfl_xor_sync(0xffffffffu, sm, 2);
            psum[wn * WW + rows[mi][h]] = sm;
        }
    }
    __syncthreads();

#pragma unroll
    for (int mi = 0; mi < 2; mi++)
#pragma unroll
        for (int h = 0; h < 2; h++)
            inv[mi][h] = 1.f / (psum[rows[mi][h]] + psum[WW + rows[mi][h]]);

#pragma unroll
    for (int mi = 0; mi < 2; mi++) {
#pragma unroll
        for (int h = 0; h < 2; h++) {
            float* rowp = S + ((size_t)(b * WW + rows[mi][h])) * MM;
#pragma unroll
            for (int ni = 0; ni < 6; ni++) {
                const int col = wn * 48 + ni * 8 + (lane & 3) * 2;
                *(float2*)(rowp + col) = make_float2(
                    acc[mi][ni][h * 2 + 0] * inv[mi][h],
                    acc[mi][ni][h * 2 + 1] * inv[mi][h]);
            }
        }
    }
}

// ---------------------------------------------------------------------------
// Scan + fused LayerNorm — direct-LDG build (no staging, no loop barriers).
// 256 threads: 128 d-lanes x 2 m-groups of 12 rows (m-chunk 24, grid 4 x BB).
// E/A loaded straight from global with a depth-1 register prefetch; the 2x
// mg duplication dedupes in L1. crow via LDS.128 broadcasts. 3 CTAs/SM.
// ---------------------------------------------------------------------------
#define UL_ROWS 12
#define UL_ASZ (2 * WW * UL_ROWS * 8)            // attn: 24576
#define UL_SMEM (UL_ASZ + 2 * 4 * UL_ROWS * 2 * 4)  // +768 = 25344

__global__ __launch_bounds__(256, 3) void update_ln_kernel(
    const float* __restrict__ mem, const float* __restrict__ attn,
    const float* __restrict__ E, const float* __restrict__ Aneg,
    const float* __restrict__ gamma, const float* __restrict__ beta,
    float* __restrict__ out)
{
    extern __shared__ __align__(16) char dsmu[];
    unsigned long long* a_s2 = (unsigned long long*)dsmu;          // [mg][w][j]
    float (*red)[4][UL_ROWS][2] = (float(*)[4][UL_ROWS][2])(dsmu + UL_ASZ);

    const int b = blockIdx.y;
    const int m0 = blockIdx.x * (2 * UL_ROWS);   // 24 rows per CTA
    const int tid = threadIdx.x;
    const int dg = tid & 127;    // d-lane: owns floats dg*4 .. dg*4+3
    const int mg = tid >> 7;     // 0..1: rows m0 + mg*UL_ROWS + j

    unsigned long long s[UL_ROWS][2];
    const float4* memp = (const float4*)mem +
        ((size_t)(b * MM + m0 + mg * UL_ROWS)) * 128 + dg;
#pragma unroll
    for (int j = 0; j < UL_ROWS; j++) {
        float4 v = memp[j * 128];
        s[j][0] = pk2(v.x, v.y);
        s[j][1] = pk2(v.z, v.w);
    }

    // attn -> smem, pre-negated & duplicated
    for (int idx = tid; idx < WW * 2 * UL_ROWS; idx += 256) {
        int w = idx / (2 * UL_ROWS), mm = idx % (2 * UL_ROWS);
        float c = attn[((size_t)(b * WW + w)) * MM + m0 + mm];
        a_s2[(mm / UL_ROWS) * (WW * UL_ROWS) + w * UL_ROWS + (mm % UL_ROWS)] =
            pk2(-c, -c);
    }
    __syncthreads();

    const ulonglong2* Ep = (const ulonglong2*)E    + (size_t)b * WW * 128 + dg;
    const ulonglong2* Ap = (const ulonglong2*)Aneg + (size_t)b * WW * 128 + dg;
    const unsigned long long* abase = a_s2 + mg * (WW * UL_ROWS);

    ulonglong2 eu = Ep[0];
    ulonglong2 au = Ap[0];
#pragma unroll 2
    for (int w = 0; w < WW; w++) {
        ulonglong2 eun = eu, aun = au;
        if (w + 1 < WW) {
            eun = Ep[(w + 1) * 128];
            aun = Ap[(w + 1) * 128];
        }
        const ulonglong2* crow2 = (const ulonglong2*)(abase + w * UL_ROWS);
#pragma unroll
        for (int t = 0; t < UL_ROWS / 2; t++) {
            ulonglong2 cc = crow2[t];
            const int j0 = 2 * t, j1 = 2 * t + 1;
            s[j0][0] = fma2(cc.x, fma2(eu.x, s[j0][0], au.x), s[j0][0]);
            s[j0][1] = fma2(cc.x, fma2(eu.y, s[j0][1], au.y), s[j0][1]);
            s[j1][0] = fma2(cc.y, fma2(eu.x, s[j1][0], au.x), s[j1][0]);
            s[j1][1] = fma2(cc.y, fma2(eu.y, s[j1][1], au.y), s[j1][1]);
        }
        eu = eun;
        au = aun;
    }

    // per-row LayerNorm: reduce over 128 d-lanes (4 warps per m-group)
    const int wg = (tid >> 5) & 3;
    const int lane = tid & 31;
#pragma unroll
    for (int j = 0; j < UL_ROWS; j++) {
        float x0, x1, x2, x3;
        upk2(x0, x1, s[j][0]);
        upk2(x2, x3, s[j][1]);
        float sm = x0 + x1 + x2 + x3;
        float sq = fmaf(x0, x0, fmaf(x1, x1, fmaf(x2, x2, x3 * x3)));
#pragma unroll
        for (int o = 16; o > 0; o >>= 1) {
            sm += __shfl_xor_sync(0xffffffffu, sm, o);
            sq += __shfl_xor_sync(0xffffffffu, sq, o);
        }
        if (lane == 0) { red[mg][wg][j][0] = sm; red[mg][wg][j][1] = sq; }
    }
    __syncthreads();

    const float4 g4 = ((const float4*)gamma)[dg];
    const float4 bt4 = ((const float4*)beta)[dg];
    float4* outp = (float4*)out + ((size_t)(b * MM + m0 + mg * UL_ROWS)) * 128 + dg;

#pragma unroll
    for (int j = 0; j < UL_ROWS; j++) {
        float Ssum = red[mg][0][j][0] + red[mg][1][j][0] + red[mg][2][j][0] + red[mg][3][j][0];
        float Qsum = red[mg][0][j][1] + red[mg][1][j][1] + red[mg][2][j][1] + red[mg][3][j][1];
        float mu = Ssum * (1.f / 512.f);
        float var = Qsum * (1.f / 512.f) - mu * mu;
        float rs = rsqrtf(var + 1e-5f);
        float x0, x1, x2, x3;
        upk2(x0, x1, s[j][0]);
        upk2(x2, x3, s[j][1]);
        float4 o;
        o.x = fmaf((x0 - mu) * rs, g4.x, bt4.x);
        o.y = fmaf((x1 - mu) * rs, g4.y, bt4.y);
        o.z = fmaf((x2 - mu) * rs, g4.z, bt4.z);
        o.w = fmaf((x3 - mu) * rs, g4.w, bt4.w);
        outp[j * 128] = o;
    }
}

// ---------------------------------------------------------------------------
extern "C" void kernel_launch(void* const* d_in, const int* in_sizes, int n_in,
                              void* d_out, int out_size)
{
    const float* memory = (const float*)d_in[0];
    const float* wtok   = (const float*)d_in[1];
    const float* Wq = (const float*)d_in[2];  const float* bq = (const float*)d_in[3];
    const float* Wk = (const float*)d_in[4];  const float* bk = (const float*)d_in[5];
    const float* We = (const float*)d_in[6];  const float* be = (const float*)d_in[7];
    const float* Wa = (const float*)d_in[8];  const float* ba = (const float*)d_in[9];
    const float* gamma = (const float*)d_in[10];
    const float* beta  = (const float*)d_in[11];
    float* out = (float*)d_out;

    float *e, *a, *s;
    __nv_bfloat16 *qb, *kb, *wt_bf, *m_bf, *wq_bf, *wk_bf, *we_bf, *wa_bf;
    cudaGetSymbolAddress((void**)&e, g_e);
    cudaGetSymbolAddress((void**)&a, g_a);
    cudaGetSymbolAddress((void**)&s, g_s);
    cudaGetSymbolAddress((void**)&qb, g_qb);
    cudaGetSymbolAddress((void**)&kb, g_kb);
    cudaGetSymbolAddress((void**)&wt_bf, g_wtok_bf);
    cudaGetSymbolAddress((void**)&m_bf, g_mem_bf);
    cudaGetSymbolAddress((void**)&wq_bf, g_Wq_bf);
    cudaGetSymbolAddress((void**)&wk_bf, g_Wk_bf);
    cudaGetSymbolAddress((void**)&we_bf, g_We_bf);
    cudaGetSymbolAddress((void**)&wa_bf, g_Wa_bf);

    static int smem_set = 0;
    if (!smem_set) {
        cudaFuncSetAttribute(all_gemm_kernel,
                             cudaFuncAttributeMaxDynamicSharedMemorySize, GEMM_SMEM);
        cudaFuncSetAttribute(scores_softmax_kernel,
                             cudaFuncAttributeMaxDynamicSharedMemorySize, SC_SMEM);
        cudaFuncSetAttribute(update_ln_kernel,
                             cudaFuncAttributeMaxDynamicSharedMemorySize, UL_SMEM);
        smem_set = 1;
    }

    // launch 0: ALL fp32->bf16 conversions
    f2bf_all_kernel<<<2048, 256>>>(
        (const float4*)wtok, (uint2*)wt_bf,
        (const float4*)memory, (uint2*)m_bf,
        (const float4*)Wq, (const float4*)Wk, (const float4*)We, (const float4*)Wa,
        (uint2*)wq_bf, (uint2*)wk_bf, (uint2*)we_bf, (uint2*)wa_bf);

    // launch 1: all four projections
    all_gemm_kernel<<<dim3(16, BB * WW / GBM), 256, GEMM_SMEM>>>(
        wt_bf, m_bf, wq_bf, we_bf, wa_bf, wk_bf,
        bq, be, ba, bk, qb, e, a, kb);

    // launch 2: fused scores + softmax
    scores_softmax_kernel<<<BB, 256, SC_SMEM>>>(qb, kb, s);

    // launch 3: scan + layernorm (direct-LDG, barrier-free main loop)
    update_ln_kernel<<<dim3(4, BB), 256, UL_SMEM>>>(memory, s, e, a, gamma, beta, out);
}

// round 15
// speedup vs baseline: 1.1352x; 1.1352x over previous
#include <cuda_runtime.h>
#include <cuda_bf16.h>
#include <cstdint>

// Problem constants
#define BB 256   // batch
#define MM 96    // memory slots
#define WW 128   // write tokens
#define DD 512   // embed dim

// ---------------- scratch (static device globals: allocation-free) ----------
__device__ __nv_bfloat16 g_wtok_bf[BB * WW * DD];
__device__ __nv_bfloat16 g_mem_bf[BB * MM * DD];
__device__ __nv_bfloat16 g_Wq_bf[DD * DD];
__device__ __nv_bfloat16 g_Wk_bf[DD * DD];
__device__ __nv_bfloat16 g_We_bf[DD * DD];
__device__ __nv_bfloat16 g_Wa_bf[DD * DD];

__device__ __nv_bfloat16 g_qb[BB * WW * DD];   // q bf16 (scores input)
__device__ __nv_bfloat16 g_kb[BB * MM * DD];   // k bf16 (scores input)
__device__ float g_e[BB * WW * DD];
__device__ float g_a[BB * WW * DD];            // NEGATED tanh (scan convention)
__device__ float g_s[BB * WW * MM];

static __device__ __forceinline__ uint32_t smem_u32(const void* p) {
    uint32_t a;
    asm("{ .reg .u64 t; cvta.to.shared.u64 t, %1; cvt.u32.u64 %0, t; }" : "=r"(a) : "l"(p));
    return a;
}

static __device__ __forceinline__ unsigned long long pk2(float x, float y) {
    unsigned long long r;
    asm("mov.b64 %0, {%1, %2};" : "=l"(r) : "f"(x), "f"(y));
    return r;
}
static __device__ __forceinline__ void upk2(float& x, float& y, unsigned long long r) {
    asm("mov.b64 {%0, %1}, %2;" : "=f"(x), "=f"(y) : "l"(r));
}
static __device__ __forceinline__ unsigned long long fma2(
    unsigned long long a, unsigned long long b, unsigned long long c) {
    unsigned long long d;
    asm("fma.rn.f32x2 %0, %1, %2, %3;" : "=l"(d) : "l"(a), "l"(b), "l"(c));
    return d;
}

// ---------------------------------------------------------------------------
// fp32 -> bf16: ALL conversions (wtok + memory + 4 weights) in one launch
// ---------------------------------------------------------------------------
#define N4_WT (BB * WW * DD / 4)   // 4194304
#define N4_MEM (BB * MM * DD / 4)  // 3145728
#define N4_W (DD * DD / 4)         // 65536

__global__ __launch_bounds__(256) void f2bf_all_kernel(
    const float4* __restrict__ wt, uint2* __restrict__ wtd,
    const float4* __restrict__ mem, uint2* __restrict__ memd,
    const float4* __restrict__ w0, const float4* __restrict__ w1,
    const float4* __restrict__ w2, const float4* __restrict__ w3,
    uint2* __restrict__ wd0, uint2* __restrict__ wd1,
    uint2* __restrict__ wd2, uint2* __restrict__ wd3)
{
    const int ntot = N4_WT + N4_MEM + 4 * N4_W;
    int i = blockIdx.x * 256 + threadIdx.x;
    const int stride = gridDim.x * 256;
    for (; i < ntot; i += stride) {
        const float4* src;
        uint2* dst;
        int off;
        if (i < N4_WT) { src = wt; dst = wtd; off = i; }
        else if (i < N4_WT + N4_MEM) { src = mem; dst = memd; off = i - N4_WT; }
        else {
            int j = i - N4_WT - N4_MEM;
            int mat = j >> 16;
            off = j & (N4_W - 1);
            src = (mat == 0) ? w0 : (mat == 1) ? w1 : (mat == 2) ? w2 : w3;
            dst = (mat == 0) ? wd0 : (mat == 1) ? wd1 : (mat == 2) ? wd2 : wd3;
        }
        float4 v = src[off];
        __nv_bfloat162 lo = __floats2bfloat162_rn(v.x, v.y);
        __nv_bfloat162 hi = __floats2bfloat162_rn(v.z, v.w);
        uint2 o;
        o.x = *(uint32_t*)&lo;
        o.y = *(uint32_t*)&hi;
        dst[off] = o;
    }
}

// ---------------------------------------------------------------------------
// mma.sync GEMM core: C = act(A @ Bw^T + bias)
// Tile 128x128x32, 256 threads, warp tile 64x32, m16n8k16 bf16.
// 3-stage cp.async pipeline, ONE __syncthreads per K-step.
// act: 1=sigmoid fp32, 2=NEGATED tanh fp32, 3=none bf16 out
// ---------------------------------------------------------------------------
#define GBM 128
#define GBN 128
#define GBK 32
#define LDSK 40
#define NKT (DD / GBK)            // 16
#define GEMM_ASTG (GBM * LDSK)    // bf16 elems per A stage (5120)
#define GEMM_BSTG (GBN * LDSK)
#define GEMM_SMEM ((3 * GEMM_ASTG + 3 * GEMM_BSTG) * 2)   // 61440 B

static __device__ __forceinline__ void gemm_tile(
    const __nv_bfloat16* __restrict__ A,
    const __nv_bfloat16* __restrict__ Bw,
    const float* __restrict__ bias,
    void* __restrict__ Cv,
    long rowbase, int colbase, int act)
{
    extern __shared__ __align__(128) char dsm[];
    const uint32_t sA_base = smem_u32(dsm);
    const uint32_t sB_base = sA_base + 3 * GEMM_ASTG * 2;

    const int tid = threadIdx.x;
    const int wid = tid >> 5;
    const int lane = tid & 31;
    const int wm = wid & 1;
    const int wn = wid >> 1;

    float acc[4][4][4];
#pragma unroll
    for (int mi = 0; mi < 4; mi++)
#pragma unroll
        for (int ni = 0; ni < 4; ni++)
#pragma unroll
            for (int v = 0; v < 4; v++) acc[mi][ni][v] = 0.f;

    const int ar0 = tid >> 2, ac0 = (tid & 3) * 8;
    const int c1 = tid + 256;
    const int ar1 = c1 >> 2, ac1 = (c1 & 3) * 8;

#define STAGE(buf, kt) do {                                                        \
    const int kk_ = (kt) * GBK;                                                    \
    const __nv_bfloat16* ga0 = A  + (rowbase + ar0) * DD + kk_ + ac0;              \
    const __nv_bfloat16* ga1 = A  + (rowbase + ar1) * DD + kk_ + ac1;              \
    const __nv_bfloat16* gb0 = Bw + (long)(colbase + ar0) * DD + kk_ + ac0;        \
    const __nv_bfloat16* gb1 = Bw + (long)(colbase + ar1) * DD + kk_ + ac1;        \
    uint32_t s_;                                                                   \
    s_ = sA_base + (uint32_t)((((buf) * GEMM_ASTG) + ar0 * LDSK + ac0) * 2);       \
    asm volatile("cp.async.cg.shared.global [%0], [%1], 16;\n" :: "r"(s_), "l"(ga0)); \
    s_ = sA_base + (uint32_t)((((buf) * GEMM_ASTG) + ar1 * LDSK + ac1) * 2);       \
    asm volatile("cp.async.cg.shared.global [%0], [%1], 16;\n" :: "r"(s_), "l"(ga1)); \
    s_ = sB_base + (uint32_t)((((buf) * GEMM_BSTG) + ar0 * LDSK + ac0) * 2);       \
    asm volatile("cp.async.cg.shared.global [%0], [%1], 16;\n" :: "r"(s_), "l"(gb0)); \
    s_ = sB_base + (uint32_t)((((buf) * GEMM_BSTG) + ar1 * LDSK + ac1) * 2);       \
    asm volatile("cp.async.cg.shared.global [%0], [%1], 16;\n" :: "r"(s_), "l"(gb1)); \
    asm volatile("cp.async.commit_group;\n");                                      \
} while (0)

    STAGE(0, 0);
    STAGE(1, 1);

    for (int kt = 0; kt < NKT; kt++) {
        if (kt == NKT - 1) asm volatile("cp.async.wait_group 0;\n");
        else               asm volatile("cp.async.wait_group 1;\n");
        __syncthreads();
        if (kt + 2 < NKT) {
            const int nb = (kt + 2) % 3;
            STAGE(nb, kt + 2);
        }

        const int buf = kt % 3;

        uint32_t af[2][4][4];
        uint32_t bfr[2][4][2];
#pragma unroll
        for (int ks = 0; ks < 2; ks++) {
            const int k0 = ks * 16;
#pragma unroll
            for (int mi = 0; mi < 4; mi++) {
                const int m0 = wm * 64 + mi * 16;
                uint32_t addr = sA_base + (uint32_t)((buf * GEMM_ASTG +
                    (m0 + (lane & 15)) * LDSK + k0 + ((lane >> 4) * 8)) * 2);
                asm volatile(
                    "ldmatrix.sync.aligned.m8n8.x4.shared.b16 {%0,%1,%2,%3}, [%4];\n"
                    : "=r"(af[ks][mi][0]), "=r"(af[ks][mi][1]),
                      "=r"(af[ks][mi][2]), "=r"(af[ks][mi][3])
                    : "r"(addr));
            }
#pragma unroll
            for (int nj = 0; nj < 2; nj++) {
                const int n0 = wn * 32 + nj * 16;
                uint32_t addr = sB_base + (uint32_t)((buf * GEMM_BSTG +
                    (n0 + (lane & 7) + ((lane >> 4) << 3)) * LDSK +
                    k0 + (((lane >> 3) & 1) * 8)) * 2);
                uint32_t r0, r1, r2, r3;
                asm volatile(
                    "ldmatrix.sync.aligned.m8n8.x4.shared.b16 {%0,%1,%2,%3}, [%4];\n"
                    : "=r"(r0), "=r"(r1), "=r"(r2), "=r"(r3) : "r"(addr));
                bfr[ks][nj * 2][0] = r0;     bfr[ks][nj * 2][1] = r1;
                bfr[ks][nj * 2 + 1][0] = r2; bfr[ks][nj * 2 + 1][1] = r3;
            }
        }

#pragma unroll
        for (int ks = 0; ks < 2; ks++)
#pragma unroll
            for (int mi = 0; mi < 4; mi++)
#pragma unroll
                for (int ni = 0; ni < 4; ni++)
                    asm volatile(
                        "mma.sync.aligned.m16n8k16.row.col.f32.bf16.bf16.f32 "
                        "{%0,%1,%2,%3}, {%4,%5,%6,%7}, {%8,%9}, {%0,%1,%2,%3};\n"
                        : "+f"(acc[mi][ni][0]), "+f"(acc[mi][ni][1]),
                          "+f"(acc[mi][ni][2]), "+f"(acc[mi][ni][3])
                        : "r"(af[ks][mi][0]), "r"(af[ks][mi][1]),
                          "r"(af[ks][mi][2]), "r"(af[ks][mi][3]),
                          "r"(bfr[ks][ni][0]), "r"(bfr[ks][ni][1]));
    }
#undef STAGE

    // epilogue: bias + activation (runtime act)
#pragma unroll
    for (int mi = 0; mi < 4; mi++) {
        const long r0 = rowbase + wm * 64 + mi * 16 + (lane >> 2);
#pragma unroll
        for (int ni = 0; ni < 4; ni++) {
            const int col = colbase + wn * 32 + ni * 8 + (lane & 3) * 2;
            const float b0 = bias[col], b1 = bias[col + 1];
            float v0 = acc[mi][ni][0] + b0;
            float v1 = acc[mi][ni][1] + b1;
            float v2 = acc[mi][ni][2] + b0;
            float v3 = acc[mi][ni][3] + b1;
            if (act == 1) {
                v0 = 1.f / (1.f + __expf(-v0)); v1 = 1.f / (1.f + __expf(-v1));
                v2 = 1.f / (1.f + __expf(-v2)); v3 = 1.f / (1.f + __expf(-v3));
            } else if (act == 2) {
                v0 = -tanhf(v0); v1 = -tanhf(v1);   // negated for scan FFMA2 form
                v2 = -tanhf(v2); v3 = -tanhf(v3);
            }
            if (act == 3) {
                __nv_bfloat16* Cb = (__nv_bfloat16*)Cv;
                *(__nv_bfloat162*)&Cb[r0 * DD + col] = __floats2bfloat162_rn(v0, v1);
                *(__nv_bfloat162*)&Cb[(r0 + 8) * DD + col] = __floats2bfloat162_rn(v2, v3);
            } else {
                float* C = (float*)Cv;
                *(float2*)&C[r0 * DD + col] = make_float2(v0, v1);
                *(float2*)&C[(r0 + 8) * DD + col] = make_float2(v2, v3);
            }
        }
    }
}

// All 4 projections, ONE gemm_tile call site. Grid: x = (mat,col), y = rowtile.
__global__ __launch_bounds__(256) void all_gemm_kernel(
    const __nv_bfloat16* __restrict__ Awt, const __nv_bfloat16* __restrict__ Am,
    const __nv_bfloat16* __restrict__ Wq, const __nv_bfloat16* __restrict__ We,
    const __nv_bfloat16* __restrict__ Wa, const __nv_bfloat16* __restrict__ Wk,
    const float* __restrict__ bq, const float* __restrict__ be,
    const float* __restrict__ ba, const float* __restrict__ bk,
    __nv_bfloat16* __restrict__ q_out, float* __restrict__ e_out,
    float* __restrict__ a_out, __nv_bfloat16* __restrict__ k_out)
{
    const int bn = blockIdx.x;
    const int mat = bn >> 2;
    const int colbase = (bn & 3) * GBN;
    const long rowbase = (long)blockIdx.y * GBM;

    const __nv_bfloat16* Asrc;
    const __nv_bfloat16* W;
    const float* bias;
    void* Cv;
    int act;
    if (mat == 0)      { Asrc = Awt; W = Wq; bias = bq; Cv = (void*)q_out; act = 3; }
    else if (mat == 1) { Asrc = Awt; W = We; bias = be; Cv = (void*)e_out; act = 1; }
    else if (mat == 2) { Asrc = Awt; W = Wa; bias = ba; Cv = (void*)a_out; act = 2; }
    else {
        if (blockIdx.y >= BB * MM / GBM) return;   // k has 192 row tiles
        Asrc = Am; W = Wk; bias = bk; Cv = (void*)k_out; act = 3;
    }
    gemm_tile(Asrc, W, bias, Cv, rowbase, colbase, act);
}

// ---------------------------------------------------------------------------
// Fused scores + softmax (mma.sync), 3-stage pipeline, one barrier per K-step.
// ---------------------------------------------------------------------------
#define SC_QSTG (WW * LDSK)
#define SC_KSTG (MM * LDSK)
#define SC_SMEM ((3 * SC_QSTG + 3 * SC_KSTG) * 2 + 2048)

__global__ __launch_bounds__(256) void scores_softmax_kernel(
    const __nv_bfloat16* __restrict__ Q, const __nv_bfloat16* __restrict__ K,
    float* __restrict__ S)
{
    extern __shared__ __align__(128) char dsm[];
    const uint32_t sQ_base = smem_u32(dsm);
    const uint32_t sK_base = sQ_base + 3 * SC_QSTG * 2;
    float* pmax = (float*)(dsm + (3 * SC_QSTG + 3 * SC_KSTG) * 2);
    float* psum = pmax + 2 * WW;

    const int b = blockIdx.x;
    const int tid = threadIdx.x;
    const int wid = tid >> 5;
    const int lane = tid & 31;
    const int wm = wid & 3;
    const int wn = wid >> 2;

    const __nv_bfloat16* Qb = Q + (size_t)b * WW * DD;
    const __nv_bfloat16* Kb = K + (size_t)b * MM * DD;

    float acc[2][6][4];
#pragma unroll
    for (int mi = 0; mi < 2; mi++)
#pragma unroll
        for (int ni = 0; ni < 6; ni++)
#pragma unroll
            for (int v = 0; v < 4; v++) acc[mi][ni][v] = 0.f;

    const int qr0 = tid >> 2, qc0 = (tid & 3) * 8;
    const int qc1i = tid + 256;
    const int qr1 = qc1i >> 2, qc1 = (qc1i & 3) * 8;
    const int kr0 = tid >> 2, kc0 = (tid & 3) * 8;
    const int kr1 = 64 + (tid >> 2), kc1 = (tid & 3) * 8;

#define SSTAGE(buf, kt) do {                                                       \
    const int kk_ = (kt) * GBK;                                                    \
    uint32_t s_;                                                                   \
    s_ = sQ_base + (uint32_t)((((buf) * SC_QSTG) + qr0 * LDSK + qc0) * 2);         \
    asm volatile("cp.async.cg.shared.global [%0], [%1], 16;\n"                     \
                 :: "r"(s_), "l"(Qb + (size_t)qr0 * DD + kk_ + qc0));              \
    s_ = sQ_base + (uint32_t)((((buf) * SC_QSTG) + qr1 * LDSK + qc1) * 2);         \
    asm volatile("cp.async.cg.shared.global [%0], [%1], 16;\n"                     \
                 :: "r"(s_), "l"(Qb + (size_t)qr1 * DD + kk_ + qc1));              \
    s_ = sK_base + (uint32_t)((((buf) * SC_KSTG) + kr0 * LDSK + kc0) * 2);         \
    asm volatile("cp.async.cg.shared.global [%0], [%1], 16;\n"                     \
                 :: "r"(s_), "l"(Kb + (size_t)kr0 * DD + kk_ + kc0));              \
    if (tid < 128) {                                                               \
        s_ = sK_base + (uint32_t)((((buf) * SC_KSTG) + kr1 * LDSK + kc1) * 2);     \
        asm volatile("cp.async.cg.shared.global [%0], [%1], 16;\n"                 \
                     :: "r"(s_), "l"(Kb + (size_t)kr1 * DD + kk_ + kc1));          \
    }                                                                              \
    asm volatile("cp.async.commit_group;\n");                                     \
} while (0)

    SSTAGE(0, 0);
    SSTAGE(1, 1);

    for (int kt = 0; kt < NKT; kt++) {
        if (kt == NKT - 1) asm volatile("cp.async.wait_group 0;\n");
        else               asm volatile("cp.async.wait_group 1;\n");
        __syncthreads();
        if (kt + 2 < NKT) {
            const int nb = (kt + 2) % 3;
            SSTAGE(nb, kt + 2);
        }

        const int buf = kt % 3;
#pragma unroll
        for (int ks = 0; ks < 2; ks++) {
            const int k0 = ks * 16;

            uint32_t af[2][4];
#pragma unroll
            for (int mi = 0; mi < 2; mi++) {
                const int m0 = wm * 32 + mi * 16;
                uint32_t addr = sQ_base + (uint32_t)((buf * SC_QSTG +
                    (m0 + (lane & 15)) * LDSK + k0 + ((lane >> 4) * 8)) * 2);
                asm volatile(
                    "ldmatrix.sync.aligned.m8n8.x4.shared.b16 {%0,%1,%2,%3}, [%4];\n"
                    : "=r"(af[mi][0]), "=r"(af[mi][1]), "=r"(af[mi][2]), "=r"(af[mi][3])
                    : "r"(addr));
            }

            uint32_t bfr[6][2];
#pragma unroll
            for (int nj = 0; nj < 3; nj++) {
                const int n0 = wn * 48 + nj * 16;
                uint32_t addr = sK_base + (uint32_t)((buf * SC_KSTG +
                    (n0 + (lane & 7) + ((lane >> 4) << 3)) * LDSK +
                    k0 + (((lane >> 3) & 1) * 8)) * 2);
                uint32_t r0, r1, r2, r3;
                asm volatile(
                    "ldmatrix.sync.aligned.m8n8.x4.shared.b16 {%0,%1,%2,%3}, [%4];\n"
                    : "=r"(r0), "=r"(r1), "=r"(r2), "=r"(r3) : "r"(addr));
                bfr[nj * 2][0] = r0;     bfr[nj * 2][1] = r1;
                bfr[nj * 2 + 1][0] = r2; bfr[nj * 2 + 1][1] = r3;
            }

#pragma unroll
            for (int mi = 0; mi < 2; mi++)
#pragma unroll
                for (int ni = 0; ni < 6; ni++)
                    asm volatile(
                        "mma.sync.aligned.m16n8k16.row.col.f32.bf16.bf16.f32 "
                        "{%0,%1,%2,%3}, {%4,%5,%6,%7}, {%8,%9}, {%0,%1,%2,%3};\n"
                        : "+f"(acc[mi][ni][0]), "+f"(acc[mi][ni][1]),
                          "+f"(acc[mi][ni][2]), "+f"(acc[mi][ni][3])
                        : "r"(af[mi][0]), "r"(af[mi][1]), "r"(af[mi][2]), "r"(af[mi][3]),
                          "r"(bfr[ni][0]), "r"(bfr[ni][1]));
        }
    }
#undef SSTAGE

    const float scale = 0.04419417382415922f;  // 1/sqrt(512)
#pragma unroll
    for (int mi = 0; mi < 2; mi++)
#pragma unroll
        for (int ni = 0; ni < 6; ni++)
#pragma unroll
            for (int v = 0; v < 4; v++) acc[mi][ni][v] *= scale;

    int rows[2][2];
#pragma unroll
    for (int mi = 0; mi < 2; mi++) {
        rows[mi][0] = wm * 32 + mi * 16 + (lane >> 2);
        rows[mi][1] = rows[mi][0] + 8;
    }

    __syncthreads();   // smem reuse: stages dead, pmax/psum region live

#pragma unroll
    for (int mi = 0; mi < 2; mi++) {
#pragma unroll
        for (int h = 0; h < 2; h++) {
            float mx = -1e30f;
#pragma unroll
            for (int ni = 0; ni < 6; ni++) {
                mx = fmaxf(mx, acc[mi][ni][h * 2 + 0]);
                mx = fmaxf(mx, acc[mi][ni][h * 2 + 1]);
            }
            mx = fmaxf(mx, __shfl_xor_sync(0xffffffffu, mx, 1));
            mx = fmaxf(mx, __shfl_xor_sync(0xffffffffu, mx, 2));
            pmax[wn * WW + rows[mi][h]] = mx;
        }
    }
    __syncthreads();

    float inv[2][2];
#pragma unroll
    for (int mi = 0; mi < 2; mi++) {
#pragma unroll
        for (int h = 0; h < 2; h++) {
            const float gmax = fmaxf(pmax[rows[mi][h]], pmax[WW + rows[mi][h]]);
            float sm = 0.f;
#pragma unroll
            for (int ni = 0; ni < 6; ni++) {
                float e0 = __expf(acc[mi][ni][h * 2 + 0] - gmax);
                float e1 = __expf(acc[mi][ni][h * 2 + 1] - gmax);
                acc[mi][ni][h * 2 + 0] = e0;
                acc[mi][ni][h * 2 + 1] = e1;
                sm += e0 + e1;
            }
            sm += __shfl_xor_sync(0xffffffffu, sm, 1);
            sm += __shfl_xor_sync(0xffffffffu, sm, 2);
            psum[wn * WW + rows[mi][h]] = sm;
        }
    }
    __syncthreads();

#pragma unroll
    for (int mi = 0; mi < 2; mi++)
#pragma unroll
        for (int h = 0; h < 2; h++)
            inv[mi][h] = 1.f / (psum[rows[mi][h]] + psum[WW + rows[mi][h]]);

#pragma unroll
    for (int mi = 0; mi < 2; mi++) {
#pragma unroll
        for (int h = 0; h < 2; h++) {
            float* rowp = S + ((size_t)(b * WW + rows[mi][h])) * MM;
#pragma unroll
            for (int ni = 0; ni < 6; ni++) {
                const int col = wn * 48 + ni * 8 + (lane & 3) * 2;
                *(float2*)(rowp + col) = make_float2(
                    acc[mi][ni][h * 2 + 0] * inv[mi][h],
                    acc[mi][ni][h * 2 + 1] * inv[mi][h]);
            }
        }
    }
}

// ---------------------------------------------------------------------------
// Scan + fused LayerNorm — const-slot build (R13 champion).
// 512 threads: 128 d-lanes x 4 m-groups of 8 rows (m-chunk 32, grid 3 x BB).
// E/A in an 8-deep cp.async ring (2 w per 8KB stage). Outer loop unrolled in
// 8-stage super-iterations with two 4-stage phases; ALL slot indices are
// compile-time constants. One wait+sync per 4 stages (16 barriers total).
// crow via LDS.128. 2 CTAs/SM.
// ---------------------------------------------------------------------------
#define UL_ROWS 8
#define UL_ASZ (4 * WW * UL_ROWS * 8)            // attn: 32768
#define UL_STG_OFF UL_ASZ
#define UL_DEPTH 8
#define UL_STG_BYTES (UL_DEPTH * 8192)           // 65536
#define UL_RED_OFF (UL_STG_OFF + UL_STG_BYTES)   // 98304
#define UL_SMEM (UL_RED_OFF + 4 * 4 * UL_ROWS * 2 * 4)  // +1024 = 99328
#define UL_NST (WW / 2)                          // 64 stages (2 w's each)

__global__ __launch_bounds__(512, 2) void update_ln_kernel(
    const float* __restrict__ mem, const float* __restrict__ attn,
    const float* __restrict__ E, const float* __restrict__ Aneg,
    const float* __restrict__ gamma, const float* __restrict__ beta,
    float* __restrict__ out)
{
    extern __shared__ __align__(16) char dsmu[];
    unsigned long long* a_s2 = (unsigned long long*)dsmu;          // [mg][w][j]
    float (*red)[4][UL_ROWS][2] = (float(*)[4][UL_ROWS][2])(dsmu + UL_RED_OFF);
    const uint32_t stg_base = smem_u32(dsmu) + UL_STG_OFF;

    const int b = blockIdx.y;
    const int m0 = blockIdx.x * (4 * UL_ROWS);   // 32 rows per CTA
    const int tid = threadIdx.x;
    const int dg = tid & 127;    // d-lane: owns floats dg*4 .. dg*4+3
    const int mg = tid >> 7;     // 0..3: rows m0 + mg*UL_ROWS + j

    // staging geometry: one 16B chunk per thread per stage (2 w's per stage)
    const int st_w = tid >> 8;           // 0/1: which w of the pair
    const int st_isA = (tid >> 7) & 1;   // 0=E, 1=Aneg
    const int st_dg = tid & 127;
    const float* st_src_base =
        (st_isA ? Aneg : E) + (size_t)b * WW * DD + st_dg * 4;
    const uint32_t st_dst_off = (uint32_t)((st_w * 2 + st_isA) * 2048 + st_dg * 16);

// slot is a compile-time constant at every call site
#define ULSTAGE(slot, p) do {                                                  \
    const float* src_ = st_src_base + (size_t)(2 * (p) + st_w) * DD;           \
    uint32_t dst_ = stg_base + (slot) * 8192 + st_dst_off;                     \
    asm volatile("cp.async.cg.shared.global [%0], [%1], 16;\n"                 \
                 :: "r"(dst_), "l"(src_));                                     \
    asm volatile("cp.async.commit_group;\n");                                  \
} while (0)

    unsigned long long s[UL_ROWS][2];
    const float4* memp = (const float4*)mem +
        ((size_t)(b * MM + m0 + mg * UL_ROWS)) * 128 + dg;
#pragma unroll
    for (int j = 0; j < UL_ROWS; j++) {
        float4 v = memp[j * 128];
        s[j][0] = pk2(v.x, v.y);
        s[j][1] = pk2(v.z, v.w);
    }

    // prologue: stages 0..3 into slots 0..3
    ULSTAGE(0, 0); ULSTAGE(1, 1); ULSTAGE(2, 2); ULSTAGE(3, 3);

    // attn -> smem, pre-negated & duplicated
    for (int idx = tid; idx < WW * 4 * UL_ROWS; idx += 512) {
        int w = idx / (4 * UL_ROWS), mm = idx % (4 * UL_ROWS);
        float c = attn[((size_t)(b * WW + w)) * MM + m0 + mm];
        a_s2[(mm / UL_ROWS) * (WW * UL_ROWS) + w * UL_ROWS + (mm % UL_ROWS)] =
            pk2(-c, -c);
    }
    __syncthreads();

    const unsigned long long* abase = a_s2 + mg * (WW * UL_ROWS);
    const char* stg_cp = dsmu + UL_STG_OFF;

    // one 4-stage phase: compute stages p..p+3 from slots s0..s0+3 (constant)
#define ULPHASE(s0c, p) do {                                                   \
    _Pragma("unroll")                                                          \
    for (int q = 0; q < 4; q++) {                                              \
        const int sbuf = (s0c) + q;        /* compile-time */                  \
        _Pragma("unroll")                                                      \
        for (int h = 0; h < 2; h++) {                                          \
            const ulonglong2 eu = *(const ulonglong2*)                         \
                (stg_cp + sbuf * 8192 + (h * 2 + 0) * 2048 + dg * 16);         \
            const ulonglong2 au = *(const ulonglong2*)                         \
                (stg_cp + sbuf * 8192 + (h * 2 + 1) * 2048 + dg * 16);         \
            const ulonglong2* crow2 = (const ulonglong2*)                      \
                (abase + (2 * ((p) + q) + h) * UL_ROWS);                       \
            _Pragma("unroll")                                                  \
            for (int t = 0; t < UL_ROWS / 2; t++) {                            \
                ulonglong2 cc = crow2[t];                                      \
                const int j0 = 2 * t, j1 = 2 * t + 1;                          \
                s[j0][0] = fma2(cc.x, fma2(eu.x, s[j0][0], au.x), s[j0][0]);   \
                s[j0][1] = fma2(cc.x, fma2(eu.y, s[j0][1], au.y), s[j0][1]);   \
                s[j1][0] = fma2(cc.y, fma2(eu.x, s[j1][0], au.x), s[j1][0]);   \
                s[j1][1] = fma2(cc.y, fma2(eu.y, s[j1][1], au.y), s[j1][1]);   \
            }                                                                  \
        }                                                                      \
    }                                                                          \
} while (0)

    // main loop: 8 stages per super-iteration, two phases, const slots
    for (int pp = 0; pp < UL_NST; pp += 8) {
        // phase A: compute stages pp..pp+3 (slots 0..3); refill slots 4..7
        asm volatile("cp.async.wait_group 0;\n");
        __syncthreads();
        ULSTAGE(4, pp + 4); ULSTAGE(5, pp + 5);
        ULSTAGE(6, pp + 6); ULSTAGE(7, pp + 7);
        ULPHASE(0, pp);

        // phase B: compute stages pp+4..pp+7 (slots 4..7); refill slots 0..3
        asm volatile("cp.async.wait_group 0;\n");
        __syncthreads();
        if (pp + 8 < UL_NST) {
            ULSTAGE(0, pp + 8);  ULSTAGE(1, pp + 9);
            ULSTAGE(2, pp + 10); ULSTAGE(3, pp + 11);
        }
        ULPHASE(4, pp + 4);
    }
#undef ULSTAGE
#undef ULPHASE

    // per-row LayerNorm: reduce over 128 d-lanes (4 warps per m-group)
    const int wg = (tid >> 5) & 3;
    const int lane = tid & 31;
#pragma unroll
    for (int j = 0; j < UL_ROWS; j++) {
        float x0, x1, x2, x3;
        upk2(x0, x1, s[j][0]);
        upk2(x2, x3, s[j][1]);
        float sm = x0 + x1 + x2 + x3;
        float sq = fmaf(x0, x0, fmaf(x1, x1, fmaf(x2, x2, x3 * x3)));
#pragma unroll
        for (int o = 16; o > 0; o >>= 1) {
            sm += __shfl_xor_sync(0xffffffffu, sm, o);
            sq += __shfl_xor_sync(0xffffffffu, sq, o);
        }
        if (lane == 0) { red[mg][wg][j][0] = sm; red[mg][wg][j][1] = sq; }
    }
    __syncthreads();

    const float4 g4 = ((const float4*)gamma)[dg];
    const float4 bt4 = ((const float4*)beta)[dg];
    float4* outp = (float4*)out + ((size_t)(b * MM + m0 + mg * UL_ROWS)) * 128 + dg;

#pragma unroll
    for (int j = 0; j < UL_ROWS; j++) {
        float Ssum = red[mg][0][j][0] + red[mg][1][j][0] + red[mg][2][j][0] + red[mg][3][j][0];
        float Qsum = red[mg][0][j][1] + red[mg][1][j][1] + red[mg][2][j][1] + red[mg][3][j][1];
        float mu = Ssum * (1.f / 512.f);
        float var = Qsum * (1.f / 512.f) - mu * mu;
        float rs = rsqrtf(var + 1e-5f);
        float x0, x1, x2, x3;
        upk2(x0, x1, s[j][0]);
        upk2(x2, x3, s[j][1]);
        float4 o;
        o.x = fmaf((x0 - mu) * rs, g4.x, bt4.x);
        o.y = fmaf((x1 - mu) * rs, g4.y, bt4.y);
        o.z = fmaf((x2 - mu) * rs, g4.z, bt4.z);
        o.w = fmaf((x3 - mu) * rs, g4.w, bt4.w);
        outp[j * 128] = o;
    }
}

// ---------------------------------------------------------------------------
extern "C" void kernel_launch(void* const* d_in, const int* in_sizes, int n_in,
                              void* d_out, int out_size)
{
    const float* memory = (const float*)d_in[0];
    const float* wtok   = (const float*)d_in[1];
    const float* Wq = (const float*)d_in[2];  const float* bq = (const float*)d_in[3];
    const float* Wk = (const float*)d_in[4];  const float* bk = (const float*)d_in[5];
    const float* We = (const float*)d_in[6];  const float* be = (const float*)d_in[7];
    const float* Wa = (const float*)d_in[8];  const float* ba = (const float*)d_in[9];
    const float* gamma = (const float*)d_in[10];
    const float* beta  = (const float*)d_in[11];
    float* out = (float*)d_out;

    float *e, *a, *s;
    __nv_bfloat16 *qb, *kb, *wt_bf, *m_bf, *wq_bf, *wk_bf, *we_bf, *wa_bf;
    cudaGetSymbolAddress((void**)&e, g_e);
    cudaGetSymbolAddress((void**)&a, g_a);
    cudaGetSymbolAddress((void**)&s, g_s);
    cudaGetSymbolAddress((void**)&qb, g_qb);
    cudaGetSymbolAddress((void**)&kb, g_kb);
    cudaGetSymbolAddress((void**)&wt_bf, g_wtok_bf);
    cudaGetSymbolAddress((void**)&m_bf, g_mem_bf);
    cudaGetSymbolAddress((void**)&wq_bf, g_Wq_bf);
    cudaGetSymbolAddress((void**)&wk_bf, g_Wk_bf);
    cudaGetSymbolAddress((void**)&we_bf, g_We_bf);
    cudaGetSymbolAddress((void**)&wa_bf, g_Wa_bf);

    static int smem_set = 0;
    if (!smem_set) {
        cudaFuncSetAttribute(all_gemm_kernel,
                             cudaFuncAttributeMaxDynamicSharedMemorySize, GEMM_SMEM);
        cudaFuncSetAttribute(scores_softmax_kernel,
                             cudaFuncAttributeMaxDynamicSharedMemorySize, SC_SMEM);
        cudaFuncSetAttribute(update_ln_kernel,
                             cudaFuncAttributeMaxDynamicSharedMemorySize, UL_SMEM);
        smem_set = 1;
    }

    // launch 0: ALL fp32->bf16 conversions
    f2bf_all_kernel<<<2048, 256>>>(
        (const float4*)wtok, (uint2*)wt_bf,
        (const float4*)memory, (uint2*)m_bf,
        (const float4*)Wq, (const float4*)Wk, (const float4*)We, (const float4*)Wa,
        (uint2*)wq_bf, (uint2*)wk_bf, (uint2*)we_bf, (uint2*)wa_bf);

    // launch 1: all four projections
    all_gemm_kernel<<<dim3(16, BB * WW / GBM), 256, GEMM_SMEM>>>(
        wt_bf, m_bf, wq_bf, we_bf, wa_bf, wk_bf,
        bq, be, ba, bk, qb, e, a, kb);

    // launch 2: fused scores + softmax
    scores_softmax_kernel<<<BB, 256, SC_SMEM>>>(qb, kb, s);

    // launch 3: scan + layernorm (const-slot ring, 16 barriers — R13 champion)
    update_ln_kernel<<<dim3(3, BB), 512, UL_SMEM>>>(memory, s, e, a, gamma, beta, out);
}

// round 16
// speedup vs baseline: 1.1596x; 1.0215x over previous
#include <cuda_runtime.h>
#include <cuda_bf16.h>
#include <cstdint>

// Problem constants
#define BB 256   // batch
#define MM 96    // memory slots
#define WW 128   // write tokens
#define DD 512   // embed dim

// ---------------- scratch (static device globals: allocation-free) ----------
__device__ __nv_bfloat16 g_wtok_bf[BB * WW * DD];
__device__ __nv_bfloat16 g_mem_bf[BB * MM * DD];
__device__ __nv_bfloat16 g_Wq_bf[DD * DD];
__device__ __nv_bfloat16 g_Wk_bf[DD * DD];
__device__ __nv_bfloat16 g_We_bf[DD * DD];
__device__ __nv_bfloat16 g_Wa_bf[DD * DD];

__device__ __nv_bfloat16 g_qb[BB * WW * DD];   // q bf16 (scores input)
__device__ __nv_bfloat16 g_kb[BB * MM * DD];   // k bf16 (scores input)
__device__ float g_e[BB * WW * DD];
__device__ float g_a[BB * WW * DD];            // NEGATED tanh (scan convention)
__device__ float g_s[BB * WW * MM];

static __device__ __forceinline__ uint32_t smem_u32(const void* p) {
    uint32_t a;
    asm("{ .reg .u64 t; cvta.to.shared.u64 t, %1; cvt.u32.u64 %0, t; }" : "=r"(a) : "l"(p));
    return a;
}

static __device__ __forceinline__ unsigned long long pk2(float x, float y) {
    unsigned long long r;
    asm("mov.b64 %0, {%1, %2};" : "=l"(r) : "f"(x), "f"(y));
    return r;
}
static __device__ __forceinline__ void upk2(float& x, float& y, unsigned long long r) {
    asm("mov.b64 {%0, %1}, %2;" : "=f"(x), "=f"(y) : "l"(r));
}
static __device__ __forceinline__ unsigned long long fma2(
    unsigned long long a, unsigned long long b, unsigned long long c) {
    unsigned long long d;
    asm("fma.rn.f32x2 %0, %1, %2, %3;" : "=l"(d) : "l"(a), "l"(b), "l"(c));
    return d;
}

// ---------------------------------------------------------------------------
// fp32 -> bf16: ALL conversions (wtok + memory + 4 weights) in one launch
// ---------------------------------------------------------------------------
#define N4_WT (BB * WW * DD / 4)   // 4194304
#define N4_MEM (BB * MM * DD / 4)  // 3145728
#define N4_W (DD * DD / 4)         // 65536

__global__ __launch_bounds__(256) void f2bf_all_kernel(
    const float4* __restrict__ wt, uint2* __restrict__ wtd,
    const float4* __restrict__ mem, uint2* __restrict__ memd,
    const float4* __restrict__ w0, const float4* __restrict__ w1,
    const float4* __restrict__ w2, const float4* __restrict__ w3,
    uint2* __restrict__ wd0, uint2* __restrict__ wd1,
    uint2* __restrict__ wd2, uint2* __restrict__ wd3)
{
    const int ntot = N4_WT + N4_MEM + 4 * N4_W;
    int i = blockIdx.x * 256 + threadIdx.x;
    const int stride = gridDim.x * 256;
    for (; i < ntot; i += stride) {
        const float4* src;
        uint2* dst;
        int off;
        if (i < N4_WT) { src = wt; dst = wtd; off = i; }
        else if (i < N4_WT + N4_MEM) { src = mem; dst = memd; off = i - N4_WT; }
        else {
            int j = i - N4_WT - N4_MEM;
            int mat = j >> 16;
            off = j & (N4_W - 1);
            src = (mat == 0) ? w0 : (mat == 1) ? w1 : (mat == 2) ? w2 : w3;
            dst = (mat == 0) ? wd0 : (mat == 1) ? wd1 : (mat == 2) ? wd2 : wd3;
        }
        float4 v = src[off];
        __nv_bfloat162 lo = __floats2bfloat162_rn(v.x, v.y);
        __nv_bfloat162 hi = __floats2bfloat162_rn(v.z, v.w);
        uint2 o;
        o.x = *(uint32_t*)&lo;
        o.y = *(uint32_t*)&hi;
        dst[off] = o;
    }
}

// ---------------------------------------------------------------------------
// mma.sync GEMM core: C = act(A @ Bw^T + bias)
// Tile 128x128x32, 256 threads, warp tile 64x32, m16n8k16 bf16.
// 3-stage cp.async pipeline, ONE __syncthreads per K-step.
// act: 1=sigmoid fp32, 2=NEGATED tanh fp32, 3=none bf16 out
// ---------------------------------------------------------------------------
#define GBM 128
#define GBN 128
#define GBK 32
#define LDSK 40
#define NKT (DD / GBK)            // 16
#define GEMM_ASTG (GBM * LDSK)    // bf16 elems per A stage (5120)
#define GEMM_BSTG (GBN * LDSK)
#define GEMM_SMEM ((3 * GEMM_ASTG + 3 * GEMM_BSTG) * 2)   // 61440 B

static __device__ __forceinline__ void gemm_tile(
    const __nv_bfloat16* __restrict__ A,
    const __nv_bfloat16* __restrict__ Bw,
    const float* __restrict__ bias,
    void* __restrict__ Cv,
    long rowbase, int colbase, int act)
{
    extern __shared__ __align__(128) char dsm[];
    const uint32_t sA_base = smem_u32(dsm);
    const uint32_t sB_base = sA_base + 3 * GEMM_ASTG * 2;

    const int tid = threadIdx.x;
    const int wid = tid >> 5;
    const int lane = tid & 31;
    const int wm = wid & 1;
    const int wn = wid >> 1;

    float acc[4][4][4];
#pragma unroll
    for (int mi = 0; mi < 4; mi++)
#pragma unroll
        for (int ni = 0; ni < 4; ni++)
#pragma unroll
            for (int v = 0; v < 4; v++) acc[mi][ni][v] = 0.f;

    const int ar0 = tid >> 2, ac0 = (tid & 3) * 8;
    const int c1 = tid + 256;
    const int ar1 = c1 >> 2, ac1 = (c1 & 3) * 8;

#define STAGE(buf, kt) do {                                                        \
    const int kk_ = (kt) * GBK;                                                    \
    const __nv_bfloat16* ga0 = A  + (rowbase + ar0) * DD + kk_ + ac0;              \
    const __nv_bfloat16* ga1 = A  + (rowbase + ar1) * DD + kk_ + ac1;              \
    const __nv_bfloat16* gb0 = Bw + (long)(colbase + ar0) * DD + kk_ + ac0;        \
    const __nv_bfloat16* gb1 = Bw + (long)(colbase + ar1) * DD + kk_ + ac1;        \
    uint32_t s_;                                                                   \
    s_ = sA_base + (uint32_t)((((buf) * GEMM_ASTG) + ar0 * LDSK + ac0) * 2);       \
    asm volatile("cp.async.cg.shared.global [%0], [%1], 16;\n" :: "r"(s_), "l"(ga0)); \
    s_ = sA_base + (uint32_t)((((buf) * GEMM_ASTG) + ar1 * LDSK + ac1) * 2);       \
    asm volatile("cp.async.cg.shared.global [%0], [%1], 16;\n" :: "r"(s_), "l"(ga1)); \
    s_ = sB_base + (uint32_t)((((buf) * GEMM_BSTG) + ar0 * LDSK + ac0) * 2);       \
    asm volatile("cp.async.cg.shared.global [%0], [%1], 16;\n" :: "r"(s_), "l"(gb0)); \
    s_ = sB_base + (uint32_t)((((buf) * GEMM_BSTG) + ar1 * LDSK + ac1) * 2);       \
    asm volatile("cp.async.cg.shared.global [%0], [%1], 16;\n" :: "r"(s_), "l"(gb1)); \
    asm volatile("cp.async.commit_group;\n");                                      \
} while (0)

    STAGE(0, 0);
    STAGE(1, 1);

    for (int kt = 0; kt < NKT; kt++) {
        if (kt == NKT - 1) asm volatile("cp.async.wait_group 0;\n");
        else               asm volatile("cp.async.wait_group 1;\n");
        __syncthreads();
        if (kt + 2 < NKT) {
            const int nb = (kt + 2) % 3;
            STAGE(nb, kt + 2);
        }

        const int buf = kt % 3;

        uint32_t af[2][4][4];
        uint32_t bfr[2][4][2];
#pragma unroll
        for (int ks = 0; ks < 2; ks++) {
            const int k0 = ks * 16;
#pragma unroll
            for (int mi = 0; mi < 4; mi++) {
                const int m0 = wm * 64 + mi * 16;
                uint32_t addr = sA_base + (uint32_t)((buf * GEMM_ASTG +
                    (m0 + (lane & 15)) * LDSK + k0 + ((lane >> 4) * 8)) * 2);
                asm volatile(
                    "ldmatrix.sync.aligned.m8n8.x4.shared.b16 {%0,%1,%2,%3}, [%4];\n"
                    : "=r"(af[ks][mi][0]), "=r"(af[ks][mi][1]),
                      "=r"(af[ks][mi][2]), "=r"(af[ks][mi][3])
                    : "r"(addr));
            }
#pragma unroll
            for (int nj = 0; nj < 2; nj++) {
                const int n0 = wn * 32 + nj * 16;
                uint32_t addr = sB_base + (uint32_t)((buf * GEMM_BSTG +
                    (n0 + (lane & 7) + ((lane >> 4) << 3)) * LDSK +
                    k0 + (((lane >> 3) & 1) * 8)) * 2);
                uint32_t r0, r1, r2, r3;
                asm volatile(
                    "ldmatrix.sync.aligned.m8n8.x4.shared.b16 {%0,%1,%2,%3}, [%4];\n"
                    : "=r"(r0), "=r"(r1), "=r"(r2), "=r"(r3) : "r"(addr));
                bfr[ks][nj * 2][0] = r0;     bfr[ks][nj * 2][1] = r1;
                bfr[ks][nj * 2 + 1][0] = r2; bfr[ks][nj * 2 + 1][1] = r3;
            }
        }

#pragma unroll
        for (int ks = 0; ks < 2; ks++)
#pragma unroll
            for (int mi = 0; mi < 4; mi++)
#pragma unroll
                for (int ni = 0; ni < 4; ni++)
                    asm volatile(
                        "mma.sync.aligned.m16n8k16.row.col.f32.bf16.bf16.f32 "
                        "{%0,%1,%2,%3}, {%4,%5,%6,%7}, {%8,%9}, {%0,%1,%2,%3};\n"
                        : "+f"(acc[mi][ni][0]), "+f"(acc[mi][ni][1]),
                          "+f"(acc[mi][ni][2]), "+f"(acc[mi][ni][3])
                        : "r"(af[ks][mi][0]), "r"(af[ks][mi][1]),
                          "r"(af[ks][mi][2]), "r"(af[ks][mi][3]),
                          "r"(bfr[ks][ni][0]), "r"(bfr[ks][ni][1]));
    }
#undef STAGE

    // epilogue: bias + activation (runtime act)
#pragma unroll
    for (int mi = 0; mi < 4; mi++) {
        const long r0 = rowbase + wm * 64 + mi * 16 + (lane >> 2);
#pragma unroll
        for (int ni = 0; ni < 4; ni++) {
            const int col = colbase + wn * 32 + ni * 8 + (lane & 3) * 2;
            const float b0 = bias[col], b1 = bias[col + 1];
            float v0 = acc[mi][ni][0] + b0;
            float v1 = acc[mi][ni][1] + b1;
            float v2 = acc[mi][ni][2] + b0;
            float v3 = acc[mi][ni][3] + b1;
            if (act == 1) {
                v0 = 1.f / (1.f + __expf(-v0)); v1 = 1.f / (1.f + __expf(-v1));
                v2 = 1.f / (1.f + __expf(-v2)); v3 = 1.f / (1.f + __expf(-v3));
            } else if (act == 2) {
                v0 = -tanhf(v0); v1 = -tanhf(v1);   // negated for scan FFMA2 form
                v2 = -tanhf(v2); v3 = -tanhf(v3);
            }
            if (act == 3) {
                __nv_bfloat16* Cb = (__nv_bfloat16*)Cv;
                *(__nv_bfloat162*)&Cb[r0 * DD + col] = __floats2bfloat162_rn(v0, v1);
                *(__nv_bfloat162*)&Cb[(r0 + 8) * DD + col] = __floats2bfloat162_rn(v2, v3);
            } else {
                float* C = (float*)Cv;
                *(float2*)&C[r0 * DD + col] = make_float2(v0, v1);
                *(float2*)&C[(r0 + 8) * DD + col] = make_float2(v2, v3);
            }
        }
    }
}

// All 4 projections, ONE gemm_tile call site. Grid: x = (mat,col), y = rowtile.
__global__ __launch_bounds__(256) void all_gemm_kernel(
    const __nv_bfloat16* __restrict__ Awt, const __nv_bfloat16* __restrict__ Am,
    const __nv_bfloat16* __restrict__ Wq, const __nv_bfloat16* __restrict__ We,
    const __nv_bfloat16* __restrict__ Wa, const __nv_bfloat16* __restrict__ Wk,
    const float* __restrict__ bq, const float* __restrict__ be,
    const float* __restrict__ ba, const float* __restrict__ bk,
    __nv_bfloat16* __restrict__ q_out, float* __restrict__ e_out,
    float* __restrict__ a_out, __nv_bfloat16* __restrict__ k_out)
{
    const int bn = blockIdx.x;
    const int mat = bn >> 2;
    const int colbase = (bn & 3) * GBN;
    const long rowbase = (long)blockIdx.y * GBM;

    const __nv_bfloat16* Asrc;
    const __nv_bfloat16* W;
    const float* bias;
    void* Cv;
    int act;
    if (mat == 0)      { Asrc = Awt; W = Wq; bias = bq; Cv = (void*)q_out; act = 3; }
    else if (mat == 1) { Asrc = Awt; W = We; bias = be; Cv = (void*)e_out; act = 1; }
    else if (mat == 2) { Asrc = Awt; W = Wa; bias = ba; Cv = (void*)a_out; act = 2; }
    else {
        if (blockIdx.y >= BB * MM / GBM) return;   // k has 192 row tiles
        Asrc = Am; W = Wk; bias = bk; Cv = (void*)k_out; act = 3;
    }
    gemm_tile(Asrc, W, bias, Cv, rowbase, colbase, act);
}

// ---------------------------------------------------------------------------
// Fused scores + softmax (mma.sync), 3-stage pipeline, one barrier per K-step.
// ---------------------------------------------------------------------------
#define SC_QSTG (WW * LDSK)
#define SC_KSTG (MM * LDSK)
#define SC_SMEM ((3 * SC_QSTG + 3 * SC_KSTG) * 2 + 2048)

__global__ __launch_bounds__(256) void scores_softmax_kernel(
    const __nv_bfloat16* __restrict__ Q, const __nv_bfloat16* __restrict__ K,
    float* __restrict__ S)
{
    extern __shared__ __align__(128) char dsm[];
    const uint32_t sQ_base = smem_u32(dsm);
    const uint32_t sK_base = sQ_base + 3 * SC_QSTG * 2;
    float* pmax = (float*)(dsm + (3 * SC_QSTG + 3 * SC_KSTG) * 2);
    float* psum = pmax + 2 * WW;

    const int b = blockIdx.x;
    const int tid = threadIdx.x;
    const int wid = tid >> 5;
    const int lane = tid & 31;
    const int wm = wid & 3;
    const int wn = wid >> 2;

    const __nv_bfloat16* Qb = Q + (size_t)b * WW * DD;
    const __nv_bfloat16* Kb = K + (size_t)b * MM * DD;

    float acc[2][6][4];
#pragma unroll
    for (int mi = 0; mi < 2; mi++)
#pragma unroll
        for (int ni = 0; ni < 6; ni++)
#pragma unroll
            for (int v = 0; v < 4; v++) acc[mi][ni][v] = 0.f;

    const int qr0 = tid >> 2, qc0 = (tid & 3) * 8;
    const int qc1i = tid + 256;
    const int qr1 = qc1i >> 2, qc1 = (qc1i & 3) * 8;
    const int kr0 = tid >> 2, kc0 = (tid & 3) * 8;
    const int kr1 = 64 + (tid >> 2), kc1 = (tid & 3) * 8;

#define SSTAGE(buf, kt) do {                                                       \
    const int kk_ = (kt) * GBK;                                                    \
    uint32_t s_;                                                                   \
    s_ = sQ_base + (uint32_t)((((buf) * SC_QSTG) + qr0 * LDSK + qc0) * 2);         \
    asm volatile("cp.async.cg.shared.global [%0], [%1], 16;\n"                     \
                 :: "r"(s_), "l"(Qb + (size_t)qr0 * DD + kk_ + qc0));              \
    s_ = sQ_base + (uint32_t)((((buf) * SC_QSTG) + qr1 * LDSK + qc1) * 2);         \
    asm volatile("cp.async.cg.shared.global [%0], [%1], 16;\n"                     \
                 :: "r"(s_), "l"(Qb + (size_t)qr1 * DD + kk_ + qc1));              \
    s_ = sK_base + (uint32_t)((((buf) * SC_KSTG) + kr0 * LDSK + kc0) * 2);         \
    asm volatile("cp.async.cg.shared.global [%0], [%1], 16;\n"                     \
                 :: "r"(s_), "l"(Kb + (size_t)kr0 * DD + kk_ + kc0));              \
    if (tid < 128) {                                                               \
        s_ = sK_base + (uint32_t)((((buf) * SC_KSTG) + kr1 * LDSK + kc1) * 2);     \
        asm volatile("cp.async.cg.shared.global [%0], [%1], 16;\n"                 \
                     :: "r"(s_), "l"(Kb + (size_t)kr1 * DD + kk_ + kc1));          \
    }                                                                              \
    asm volatile("cp.async.commit_group;\n");                                     \
} while (0)

    SSTAGE(0, 0);
    SSTAGE(1, 1);

    for (int kt = 0; kt < NKT; kt++) {
        if (kt == NKT - 1) asm volatile("cp.async.wait_group 0;\n");
        else               asm volatile("cp.async.wait_group 1;\n");
        __syncthreads();
        if (kt + 2 < NKT) {
            const int nb = (kt + 2) % 3;
            SSTAGE(nb, kt + 2);
        }

        const int buf = kt % 3;
#pragma unroll
        for (int ks = 0; ks < 2; ks++) {
            const int k0 = ks * 16;

            uint32_t af[2][4];
#pragma unroll
            for (int mi = 0; mi < 2; mi++) {
                const int m0 = wm * 32 + mi * 16;
                uint32_t addr = sQ_base + (uint32_t)((buf * SC_QSTG +
                    (m0 + (lane & 15)) * LDSK + k0 + ((lane >> 4) * 8)) * 2);
                asm volatile(
                    "ldmatrix.sync.aligned.m8n8.x4.shared.b16 {%0,%1,%2,%3}, [%4];\n"
                    : "=r"(af[mi][0]), "=r"(af[mi][1]), "=r"(af[mi][2]), "=r"(af[mi][3])
                    : "r"(addr));
            }

            uint32_t bfr[6][2];
#pragma unroll
            for (int nj = 0; nj < 3; nj++) {
                const int n0 = wn * 48 + nj * 16;
                uint32_t addr = sK_base + (uint32_t)((buf * SC_KSTG +
                    (n0 + (lane & 7) + ((lane >> 4) << 3)) * LDSK +
                    k0 + (((lane >> 3) & 1) * 8)) * 2);
                uint32_t r0, r1, r2, r3;
                asm volatile(
                    "ldmatrix.sync.aligned.m8n8.x4.shared.b16 {%0,%1,%2,%3}, [%4];\n"
                    : "=r"(r0), "=r"(r1), "=r"(r2), "=r"(r3) : "r"(addr));
                bfr[nj * 2][0] = r0;     bfr[nj * 2][1] = r1;
                bfr[nj * 2 + 1][0] = r2; bfr[nj * 2 + 1][1] = r3;
            }

#pragma unroll
            for (int mi = 0; mi < 2; mi++)
#pragma unroll
                for (int ni = 0; ni < 6; ni++)
                    asm volatile(
                        "mma.sync.aligned.m16n8k16.row.col.f32.bf16.bf16.f32 "
                        "{%0,%1,%2,%3}, {%4,%5,%6,%7}, {%8,%9}, {%0,%1,%2,%3};\n"
                        : "+f"(acc[mi][ni][0]), "+f"(acc[mi][ni][1]),
                          "+f"(acc[mi][ni][2]), "+f"(acc[mi][ni][3])
                        : "r"(af[mi][0]), "r"(af[mi][1]), "r"(af[mi][2]), "r"(af[mi][3]),
                          "r"(bfr[ni][0]), "r"(bfr[ni][1]));
        }
    }
#undef SSTAGE

    const float scale = 0.04419417382415922f;  // 1/sqrt(512)
#pragma unroll
    for (int mi = 0; mi < 2; mi++)
#pragma unroll
        for (int ni = 0; ni < 6; ni++)
#pragma unroll
            for (int v = 0; v < 4; v++) acc[mi][ni][v] *= scale;

    int rows[2][2];
#pragma unroll
    for (int mi = 0; mi < 2; mi++) {
        rows[mi][0] = wm * 32 + mi * 16 + (lane >> 2);
        rows[mi][1] = rows[mi][0] + 8;
    }

    __syncthreads();   // smem reuse: stages dead, pmax/psum region live

#pragma unroll
    for (int mi = 0; mi < 2; mi++) {
#pragma unroll
        for (int h = 0; h < 2; h++) {
            float mx = -1e30f;
#pragma unroll
            for (int ni = 0; ni < 6; ni++) {
                mx = fmaxf(mx, acc[mi][ni][h * 2 + 0]);
                mx = fmaxf(mx, acc[mi][ni][h * 2 + 1]);
            }
            mx = fmaxf(mx, __shfl_xor_sync(0xffffffffu, mx, 1));
            mx = fmaxf(mx, __shfl_xor_sync(0xffffffffu, mx, 2));
            pmax[wn * WW + rows[mi][h]] = mx;
        }
    }
    __syncthreads();

    float inv[2][2];
#pragma unroll
    for (int mi = 0; mi < 2; mi++) {
#pragma unroll
        for (int h = 0; h < 2; h++) {
            const float gmax = fmaxf(pmax[rows[mi][h]], pmax[WW + rows[mi][h]]);
            float sm = 0.f;
#pragma unroll
            for (int ni = 0; ni < 6; ni++) {
                float e0 = __expf(acc[mi][ni][h * 2 + 0] - gmax);
                float e1 = __expf(acc[mi][ni][h * 2 + 1] - gmax);
                acc[mi][ni][h * 2 + 0] = e0;
                acc[mi][ni][h * 2 + 1] = e1;
                sm += e0 + e1;
            }
            sm += __shfl_xor_sync(0xffffffffu, sm, 1);
            sm += __shfl_xor_sync(0xffffffffu, sm, 2);
            psum[wn * WW + rows[mi][h]] = sm;
        }
    }
    __syncthreads();

#pragma unroll
    for (int mi = 0; mi < 2; mi++)
#pragma unroll
        for (int h = 0; h < 2; h++)
            inv[mi][h] = 1.f / (psum[rows[mi][h]] + psum[WW + rows[mi][h]]);

#pragma unroll
    for (int mi = 0; mi < 2; mi++) {
#pragma unroll
        for (int h = 0; h < 2; h++) {
            float* rowp = S + ((size_t)(b * WW + rows[mi][h])) * MM;
#pragma unroll
            for (int ni = 0; ni < 6; ni++) {
                const int col = wn * 48 + ni * 8 + (lane & 3) * 2;
                *(float2*)(rowp + col) = make_float2(
                    acc[mi][ni][h * 2 + 0] * inv[mi][h],
                    acc[mi][ni][h * 2 + 1] * inv[mi][h]);
            }
        }
    }
}

// ---------------------------------------------------------------------------
// Scan + fused LayerNorm — const-slot build (champion).
// 512 threads: 128 d-lanes x 4 m-groups of 8 rows (m-chunk 32, grid 3 x BB).
// E/A in an 8-deep cp.async ring (2 w per 8KB stage). Outer loop unrolled in
// 8-stage super-iterations with two 4-stage phases; ALL slot indices are
// compile-time constants. One wait+sync per 4 stages (16 barriers total).
// crow via LDS.128. 2 CTAs/SM.
// ---------------------------------------------------------------------------
#define UL_ROWS 8
#define UL_ASZ (4 * WW * UL_ROWS * 8)            // attn: 32768
#define UL_STG_OFF UL_ASZ
#define UL_DEPTH 8
#define UL_STG_BYTES (UL_DEPTH * 8192)           // 65536
#define UL_RED_OFF (UL_STG_OFF + UL_STG_BYTES)   // 98304
#define UL_SMEM (UL_RED_OFF + 4 * 4 * UL_ROWS * 2 * 4)  // +1024 = 99328
#define UL_NST (WW / 2)                          // 64 stages (2 w's each)

__global__ __launch_bounds__(512, 2) void update_ln_kernel(
    const float* __restrict__ mem, const float* __restrict__ attn,
    const float* __restrict__ E, const float* __restrict__ Aneg,
    const float* __restrict__ gamma, const float* __restrict__ beta,
    float* __restrict__ out)
{
    extern __shared__ __align__(16) char dsmu[];
    unsigned long long* a_s2 = (unsigned long long*)dsmu;          // [mg][w][j]
    float (*red)[4][UL_ROWS][2] = (float(*)[4][UL_ROWS][2])(dsmu + UL_RED_OFF);
    const uint32_t stg_base = smem_u32(dsmu) + UL_STG_OFF;

    const int b = blockIdx.y;
    const int m0 = blockIdx.x * (4 * UL_ROWS);   // 32 rows per CTA
    const int tid = threadIdx.x;
    const int dg = tid & 127;    // d-lane: owns floats dg*4 .. dg*4+3
    const int mg = tid >> 7;     // 0..3: rows m0 + mg*UL_ROWS + j

    // staging geometry: one 16B chunk per thread per stage (2 w's per stage)
    const int st_w = tid >> 8;           // 0/1: which w of the pair
    const int st_isA = (tid >> 7) & 1;   // 0=E, 1=Aneg
    const int st_dg = tid & 127;
    const float* st_src_base =
        (st_isA ? Aneg : E) + (size_t)b * WW * DD + st_dg * 4;
    const uint32_t st_dst_off = (uint32_t)((st_w * 2 + st_isA) * 2048 + st_dg * 16);

// slot is a compile-time constant at every call site
#define ULSTAGE(slot, p) do {                                                  \
    const float* src_ = st_src_base + (size_t)(2 * (p) + st_w) * DD;           \
    uint32_t dst_ = stg_base + (slot) * 8192 + st_dst_off;                     \
    asm volatile("cp.async.cg.shared.global [%0], [%1], 16;\n"                 \
                 :: "r"(dst_), "l"(src_));                                     \
    asm volatile("cp.async.commit_group;\n");                                  \
} while (0)

    unsigned long long s[UL_ROWS][2];
    const float4* memp = (const float4*)mem +
        ((size_t)(b * MM + m0 + mg * UL_ROWS)) * 128 + dg;
#pragma unroll
    for (int j = 0; j < UL_ROWS; j++) {
        float4 v = memp[j * 128];
        s[j][0] = pk2(v.x, v.y);
        s[j][1] = pk2(v.z, v.w);
    }

    // prologue: stages 0..3 into slots 0..3
    ULSTAGE(0, 0); ULSTAGE(1, 1); ULSTAGE(2, 2); ULSTAGE(3, 3);

    // attn -> smem, pre-negated & duplicated
    for (int idx = tid; idx < WW * 4 * UL_ROWS; idx += 512) {
        int w = idx / (4 * UL_ROWS), mm = idx % (4 * UL_ROWS);
        float c = attn[((size_t)(b * WW + w)) * MM + m0 + mm];
        a_s2[(mm / UL_ROWS) * (WW * UL_ROWS) + w * UL_ROWS + (mm % UL_ROWS)] =
            pk2(-c, -c);
    }
    __syncthreads();

    const unsigned long long* abase = a_s2 + mg * (WW * UL_ROWS);
    const char* stg_cp = dsmu + UL_STG_OFF;

    // one 4-stage phase: compute stages p..p+3 from slots s0..s0+3 (constant)
#define ULPHASE(s0c, p) do {                                                   \
    _Pragma("unroll")                                                          \
    for (int q = 0; q < 4; q++) {                                              \
        const int sbuf = (s0c) + q;        /* compile-time */                  \
        _Pragma("unroll")                                                      \
        for (int h = 0; h < 2; h++) {                                          \
            const ulonglong2 eu = *(const ulonglong2*)                         \
                (stg_cp + sbuf * 8192 + (h * 2 + 0) * 2048 + dg * 16);         \
            const ulonglong2 au = *(const ulonglong2*)                         \
                (stg_cp + sbuf * 8192 + (h * 2 + 1) * 2048 + dg * 16);         \
            const ulonglong2* crow2 = (const ulonglong2*)                      \
                (abase + (2 * ((p) + q) + h) * UL_ROWS);                       \
            _Pragma("unroll")                                                  \
            for (int t = 0; t < UL_ROWS / 2; t++) {                            \
                ulonglong2 cc = crow2[t];                                      \
                const int j0 = 2 * t, j1 = 2 * t + 1;                          \
                s[j0][0] = fma2(cc.x, fma2(eu.x, s[j0][0], au.x), s[j0][0]);   \
                s[j0][1] = fma2(cc.x, fma2(eu.y, s[j0][1], au.y), s[j0][1]);   \
                s[j1][0] = fma2(cc.y, fma2(eu.x, s[j1][0], au.x), s[j1][0]);   \
                s[j1][1] = fma2(cc.y, fma2(eu.y, s[j1][1], au.y), s[j1][1]);   \
            }                                                                  \
        }                                                                      \
    }                                                                          \
} while (0)

    // main loop: 8 stages per super-iteration, two phases, const slots
    for (int pp = 0; pp < UL_NST; pp += 8) {
        // phase A: compute stages pp..pp+3 (slots 0..3); refill slots 4..7
        asm volatile("cp.async.wait_group 0;\n");
        __syncthreads();
        ULSTAGE(4, pp + 4); ULSTAGE(5, pp + 5);
        ULSTAGE(6, pp + 6); ULSTAGE(7, pp + 7);
        ULPHASE(0, pp);

        // phase B: compute stages pp+4..pp+7 (slots 4..7); refill slots 0..3
        asm volatile("cp.async.wait_group 0;\n");
        __syncthreads();
        if (pp + 8 < UL_NST) {
            ULSTAGE(0, pp + 8);  ULSTAGE(1, pp + 9);
            ULSTAGE(2, pp + 10); ULSTAGE(3, pp + 11);
        }
        ULPHASE(4, pp + 4);
    }
#undef ULSTAGE
#undef ULPHASE

    // per-row LayerNorm: reduce over 128 d-lanes (4 warps per m-group)
    const int wg = (tid >> 5) & 3;
    const int lane = tid & 31;
#pragma unroll
    for (int j = 0; j < UL_ROWS; j++) {
        float x0, x1, x2, x3;
        upk2(x0, x1, s[j][0]);
        upk2(x2, x3, s[j][1]);
        float sm = x0 + x1 + x2 + x3;
        float sq = fmaf(x0, x0, fmaf(x1, x1, fmaf(x2, x2, x3 * x3)));
#pragma unroll
        for (int o = 16; o > 0; o >>= 1) {
            sm += __shfl_xor_sync(0xffffffffu, sm, o);
            sq += __shfl_xor_sync(0xffffffffu, sq, o);
        }
        if (lane == 0) { red[mg][wg][j][0] = sm; red[mg][wg][j][1] = sq; }
    }
    __syncthreads();

    const float4 g4 = ((const float4*)gamma)[dg];
    const float4 bt4 = ((const float4*)beta)[dg];
    float4* outp = (float4*)out + ((size_t)(b * MM + m0 + mg * UL_ROWS)) * 128 + dg;

#pragma unroll
    for (int j = 0; j < UL_ROWS; j++) {
        float Ssum = red[mg][0][j][0] + red[mg][1][j][0] + red[mg][2][j][0] + red[mg][3][j][0];
        float Qsum = red[mg][0][j][1] + red[mg][1][j][1] + red[mg][2][j][1] + red[mg][3][j][1];
        float mu = Ssum * (1.f / 512.f);
        float var = Qsum * (1.f / 512.f) - mu * mu;
        float rs = rsqrtf(var + 1e-5f);
        float x0, x1, x2, x3;
        upk2(x0, x1, s[j][0]);
        upk2(x2, x3, s[j][1]);
        float4 o;
        o.x = fmaf((x0 - mu) * rs, g4.x, bt4.x);
        o.y = fmaf((x1 - mu) * rs, g4.y, bt4.y);
        o.z = fmaf((x2 - mu) * rs, g4.z, bt4.z);
        o.w = fmaf((x3 - mu) * rs, g4.w, bt4.w);
        outp[j * 128] = o;
    }
}

// ---------------------------------------------------------------------------
extern "C" void kernel_launch(void* const* d_in, const int* in_sizes, int n_in,
                              void* d_out, int out_size)
{
    const float* memory = (const float*)d_in[0];
    const float* wtok   = (const float*)d_in[1];
    const float* Wq = (const float*)d_in[2];  const float* bq = (const float*)d_in[3];
    const float* Wk = (const float*)d_in[4];  const float* bk = (const float*)d_in[5];
    const float* We = (const float*)d_in[6];  const float* be = (const float*)d_in[7];
    const float* Wa = (const float*)d_in[8];  const float* ba = (const float*)d_in[9];
    const float* gamma = (const float*)d_in[10];
    const float* beta  = (const float*)d_in[11];
    float* out = (float*)d_out;

    float *e, *a, *s;
    __nv_bfloat16 *qb, *kb, *wt_bf, *m_bf, *wq_bf, *wk_bf, *we_bf, *wa_bf;
    cudaGetSymbolAddress((void**)&e, g_e);
    cudaGetSymbolAddress((void**)&a, g_a);
    cudaGetSymbolAddress((void**)&s, g_s);
    cudaGetSymbolAddress((void**)&qb, g_qb);
    cudaGetSymbolAddress((void**)&kb, g_kb);
    cudaGetSymbolAddress((void**)&wt_bf, g_wtok_bf);
    cudaGetSymbolAddress((void**)&m_bf, g_mem_bf);
    cudaGetSymbolAddress((void**)&wq_bf, g_Wq_bf);
    cudaGetSymbolAddress((void**)&wk_bf, g_Wk_bf);
    cudaGetSymbolAddress((void**)&we_bf, g_We_bf);
    cudaGetSymbolAddress((void**)&wa_bf, g_Wa_bf);

    static int smem_set = 0;
    if (!smem_set) {
        cudaFuncSetAttribute(all_gemm_kernel,
                             cudaFuncAttributeMaxDynamicSharedMemorySize, GEMM_SMEM);
        cudaFuncSetAttribute(scores_softmax_kernel,
                             cudaFuncAttributeMaxDynamicSharedMemorySize, SC_SMEM);
        cudaFuncSetAttribute(update_ln_kernel,
                             cudaFuncAttributeMaxDynamicSharedMemorySize, UL_SMEM);
        smem_set = 1;
    }

    // launch 0: ALL fp32->bf16 conversions
    f2bf_all_kernel<<<2048, 256>>>(
        (const float4*)wtok, (uint2*)wt_bf,
        (const float4*)memory, (uint2*)m_bf,
        (const float4*)Wq, (const float4*)Wk, (const float4*)We, (const float4*)Wa,
        (uint2*)wq_bf, (uint2*)wk_bf, (uint2*)we_bf, (uint2*)wa_bf);

    // launch 1: all four projections
    all_gemm_kernel<<<dim3(16, BB * WW / GBM), 256, GEMM_SMEM>>>(
        wt_bf, m_bf, wq_bf, we_bf, wa_bf, wk_bf,
        bq, be, ba, bk, qb, e, a, kb);

    // launch 2: fused scores + softmax
    scores_softmax_kernel<<<BB, 256, SC_SMEM>>>(qb, kb, s);

    // launch 3: scan + layernorm (const-slot ring, 16 barriers — champion)
    update_ln_kernel<<<dim3(3, BB), 512, UL_SMEM>>>(memory, s, e, a, gamma, beta, out);
}